// round 6
// baseline (speedup 1.0000x reference)
#include <cuda_runtime.h>
#include <stdint.h>
#include <math.h>

#define TOPK 1000
#define DETS 300
#define NB    4608          // bins over (0.05, 1.0] via fb>>13 - BASE
#define CH    18            // NB / 256
#define BASE  125542        // 0x3D4CCCCD >> 13  (0.05f)
#define CAND_CAP 32768
#define SELCAP   6144
#define NCLS  80
#define CLSCAP 1024
#define WCAP_S 4096

#define HIST_GRID 592
#define SEL_GRID  16

__device__ unsigned int       g_hist1[NB];
__device__ unsigned int       g_sel[8];          // [0]=B1 [2]=cand cnt [6]=hist ticket [7]=sel ticket
__device__ unsigned long long g_cand[CAND_CAP];
__device__ int                g_topIdx[TOPK];
__device__ float              g_topVal[TOPK];
__device__ float              g_bk[TOPK*5];      // original boxes (output)
__device__ float              g_nms[TOPK*5];     // offset boxes (NMS domain)
__device__ float              g_corn[TOPK*8];
__device__ float              g_aabb[TOPK*4];    // minx,maxx,miny,maxy
__device__ float              g_area[TOPK];
__device__ int                g_clsCnt[NCLS];
__device__ int                g_clsIdx[NCLS*CLSCAP];
__device__ int                g_lab[TOPK];

__device__ __forceinline__ float neginf() { return __int_as_float(0xff800000); }

__device__ __forceinline__ int bin_of(unsigned fb) {
    int b = (int)(fb >> 13) - BASE;
    if (b < 0) b = 0;
    if (b > NB - 1) b = NB - 1;
    return b;
}

// ---------------------------------------------------------------- reset
__global__ void k_reset() {
    int i  = blockIdx.x * blockDim.x + threadIdx.x;
    int st = gridDim.x * blockDim.x;
    for (int k = i; k < NB;   k += st) g_hist1[k] = 0;
    for (int k = i; k < 8;    k += st) g_sel[k]   = 0;
    for (int k = i; k < NCLS; k += st) g_clsCnt[k] = 0;
    for (int k = i; k < TOPK; k += st) {
        g_topIdx[k] = -1;
        g_topVal[k] = neginf();
    }
}

// ---------------------------------------------------------------- pass 1: histogram + fused findb1 (last block)
__global__ void k_hist(const float4* __restrict__ sc4, int n4) {
    __shared__ unsigned int h[NB];
    __shared__ unsigned csum[256];
    __shared__ int isLast;
    int tid = threadIdx.x;
    for (int k = tid; k < NB; k += blockDim.x) h[k] = 0;
    __syncthreads();
    int i0 = blockIdx.x * blockDim.x + tid;
    int S  = gridDim.x * blockDim.x;
    for (int p = i0; p < n4; p += 4 * S) {
        int p1 = p + S, p2 = p + 2*S, p3 = p + 3*S;
        float4 v0 = sc4[p];
        float4 v1 = (p1 < n4) ? sc4[p1] : make_float4(0,0,0,0);
        float4 v2 = (p2 < n4) ? sc4[p2] : make_float4(0,0,0,0);
        float4 v3 = (p3 < n4) ? sc4[p3] : make_float4(0,0,0,0);
        float vs[16] = { v0.x,v0.y,v0.z,v0.w, v1.x,v1.y,v1.z,v1.w,
                         v2.x,v2.y,v2.z,v2.w, v3.x,v3.y,v3.z,v3.w };
#pragma unroll
        for (int l = 0; l < 16; l++) {
            float s = vs[l];
            if (s > 0.05f) atomicAdd(&h[bin_of(__float_as_uint(s))], 1u);
        }
    }
    __syncthreads();
    for (int k = tid; k < NB; k += blockDim.x) {
        unsigned v = h[k];
        if (v) atomicAdd(&g_hist1[k], v);
    }
    __threadfence();
    if (tid == 0) {
        unsigned t = atomicAdd(&g_sel[6], 1u);
        isLast = (t == gridDim.x - 1);
    }
    __syncthreads();
    if (!isLast) return;
    __threadfence();
    // ---- fused findb1 ----
    for (int k = tid; k < NB; k += blockDim.x) h[k] = g_hist1[k];
    __syncthreads();
    unsigned s = 0;
    for (int b = tid * CH; b < tid * CH + CH; b++) s += h[b];
    csum[tid] = s;
    __syncthreads();
    if (tid == 0) {
        unsigned cum = 0; int B1 = -1;
        for (int c = 255; c >= 0; c--) {
            if (cum + csum[c] >= TOPK) {
                for (int b = c * CH + CH - 1; b >= c * CH; b--) {
                    if (cum + h[b] >= TOPK) { B1 = b; break; }
                    cum += h[b];
                }
                break;
            }
            cum += csum[c];
        }
        if (B1 < 0) B1 = 0;
        g_sel[0] = (unsigned)B1;
    }
}

// ---------------------------------------------------------------- pass 2: compact (bin >= B1)
__global__ void k_compact(const float4* __restrict__ sc4, int n4) {
    unsigned B1 = g_sel[0];
    int i0 = blockIdx.x * blockDim.x + threadIdx.x;
    int S  = gridDim.x * blockDim.x;
    for (int p = i0; p < n4; p += 2 * S) {
        int p1 = p + S;
        float4 v0 = sc4[p];
        float4 v1 = (p1 < n4) ? sc4[p1] : make_float4(0,0,0,0);
        float vs[8] = { v0.x,v0.y,v0.z,v0.w, v1.x,v1.y,v1.z,v1.w };
        int   pb[2] = { p, p1 };
#pragma unroll
        for (int l = 0; l < 8; l++) {
            float s = vs[l];
            if (s > 0.05f) {
                unsigned fb = __float_as_uint(s);
                if (bin_of(fb) >= (int)B1) {
                    unsigned pos = atomicAdd(&g_sel[2], 1u);
                    if (pos < CAND_CAP) {
                        unsigned idx = (unsigned)(pb[l >> 2] * 4 + (l & 3));
                        g_cand[pos] = ((unsigned long long)fb << 32) |
                                      (unsigned long long)(0xFFFFFFFFu - idx);
                    }
                }
            }
        }
    }
}

// ---------------------------------------------------------------- select (unrolled rank) + fused prep (last block)
__global__ void k_selprep(const float* __restrict__ boxes, const int* __restrict__ labels) {
    __shared__ unsigned long long sk[SELCAP];
    __shared__ int isLast;
    unsigned C = g_sel[2];
    if (C > CAND_CAP) C = CAND_CAP;
    int tid = threadIdx.x;
    int gid = blockIdx.x * blockDim.x + tid;
    int st  = gridDim.x * blockDim.x;
    if (C <= SELCAP) {
        for (unsigned k = (unsigned)tid; k < C; k += blockDim.x) sk[k] = g_cand[k];
        __syncthreads();
        for (unsigned c = (unsigned)gid; c < C; c += (unsigned)st) {
            unsigned long long key = sk[c];
            int rank = 0;
            unsigned k = 0;
            for (; k + 8 <= C; k += 8) {           // MLP=8: independent LDS batched
                unsigned long long a0 = sk[k+0], a1 = sk[k+1], a2 = sk[k+2], a3 = sk[k+3];
                unsigned long long a4 = sk[k+4], a5 = sk[k+5], a6 = sk[k+6], a7 = sk[k+7];
                rank += (a0 > key) + (a1 > key) + (a2 > key) + (a3 > key)
                      + (a4 > key) + (a5 > key) + (a6 > key) + (a7 > key);
            }
            for (; k < C; k++) rank += (sk[k] > key) ? 1 : 0;
            if (rank < TOPK) {
                g_topIdx[rank] = (int)(0xFFFFFFFFu - (unsigned)(key & 0xFFFFFFFFull));
                g_topVal[rank] = __uint_as_float((unsigned)(key >> 32));
            }
        }
    } else {
        for (unsigned c = (unsigned)gid; c < C; c += (unsigned)st) {
            unsigned long long key = g_cand[c];
            int rank = 0;
            unsigned k = 0;
            for (; k + 8 <= C; k += 8) {
                unsigned long long a0 = g_cand[k+0], a1 = g_cand[k+1], a2 = g_cand[k+2], a3 = g_cand[k+3];
                unsigned long long a4 = g_cand[k+4], a5 = g_cand[k+5], a6 = g_cand[k+6], a7 = g_cand[k+7];
                rank += (a0 > key) + (a1 > key) + (a2 > key) + (a3 > key)
                      + (a4 > key) + (a5 > key) + (a6 > key) + (a7 > key);
            }
            for (; k < C; k++) rank += (g_cand[k] > key) ? 1 : 0;
            if (rank < TOPK) {
                g_topIdx[rank] = (int)(0xFFFFFFFFu - (unsigned)(key & 0xFFFFFFFFull));
                g_topVal[rank] = __uint_as_float((unsigned)(key >> 32));
            }
        }
    }
    __threadfence();
    __syncthreads();
    if (tid == 0) {
        unsigned t = atomicAdd(&g_sel[7], 1u);
        isLast = (t == gridDim.x - 1);
    }
    __syncthreads();
    if (!isLast) return;
    __threadfence();
    // ---- fused prep: gather + offset + corners + AABB + class lists ----
    for (int i = tid; i < TOPK; i += blockDim.x) {
        int idx = g_topIdx[i];
        if (idx < 0) { g_lab[i] = -2 - i; g_area[i] = 0.0f; continue; }
        float cx = boxes[idx*5+0], cy = boxes[idx*5+1];
        float w  = boxes[idx*5+2], h  = boxes[idx*5+3];
        float a  = boxes[idx*5+4];
        g_bk[i*5+0]=cx; g_bk[i*5+1]=cy; g_bk[i*5+2]=w; g_bk[i*5+3]=h; g_bk[i*5+4]=a;
        int lab = labels[idx];
        g_lab[i] = lab;
        float off = __fmul_rn((float)lab, 10000.0f);
        float cxo = __fadd_rn(cx, off);
        float cyo = __fadd_rn(cy, off);
        g_nms[i*5+0]=cxo; g_nms[i*5+1]=cyo; g_nms[i*5+2]=w; g_nms[i*5+3]=h; g_nms[i*5+4]=a;
        g_area[i] = __fmul_rn(w, h);

        float c = cosf(a), s = sinf(a);
        float dx = __fmul_rn(w, 0.5f), dy = __fmul_rn(h, 0.5f);
        float ox[4] = { dx, -dx, -dx,  dx };
        float oy[4] = { dy,  dy, -dy, -dy };
        float mnx =  3.4e38f, mxx = -3.4e38f, mny = 3.4e38f, mxy = -3.4e38f;
#pragma unroll
        for (int j = 0; j < 4; j++) {
            float x = __fsub_rn(__fadd_rn(cxo, __fmul_rn(ox[j], c)), __fmul_rn(oy[j], s));
            float y = __fadd_rn(__fadd_rn(cyo, __fmul_rn(ox[j], s)), __fmul_rn(oy[j], c));
            g_corn[i*8 + 2*j]     = x;
            g_corn[i*8 + 2*j + 1] = y;
            mnx = fminf(mnx, x); mxx = fmaxf(mxx, x);
            mny = fminf(mny, y); mxy = fmaxf(mxy, y);
        }
        g_aabb[i*4+0]=mnx; g_aabb[i*4+1]=mxx; g_aabb[i*4+2]=mny; g_aabb[i*4+3]=mxy;
        if (lab >= 0 && lab < NCLS) {
            int pos = atomicAdd(&g_clsCnt[lab], 1);
            if (pos < CLSCAP) g_clsIdx[lab*CLSCAP + pos] = i;
        }
    }
}

// ---------------------------------------------------------------- exact replica of _pair_inter_area (fp32, no FMA, seq order)
__device__ float pair_inter_area(const float* A, const float* cA,
                                 const float* B, const float* cB) {
    const float eps = 1e-6f;
    const float ONEPE = 1.000001f;
    float px[24], py[24];
    bool  vl[24];
    float ax[4], ay[4], bx[4], by[4];
#pragma unroll
    for (int k = 0; k < 4; k++) {
        ax[k]=cA[2*k]; ay[k]=cA[2*k+1]; bx[k]=cB[2*k]; by[k]=cB[2*k+1];
        px[k]=ax[k]; py[k]=ay[k]; px[4+k]=bx[k]; py[4+k]=by[k];
    }
    {   // vA = in_box(cornA, boxB)
        float c = cosf(B[4]), s = sinf(B[4]);
        float lw = __fadd_rn(__fmul_rn(B[2], 0.5f), eps);
        float lh = __fadd_rn(__fmul_rn(B[3], 0.5f), eps);
#pragma unroll
        for (int k = 0; k < 4; k++) {
            float rx = __fsub_rn(ax[k], B[0]), ry = __fsub_rn(ay[k], B[1]);
            float xr = __fadd_rn(__fmul_rn(rx, c), __fmul_rn(ry, s));
            float yr = __fadd_rn(__fmul_rn(-rx, s), __fmul_rn(ry, c));
            vl[k] = (fabsf(xr) <= lw) && (fabsf(yr) <= lh);
        }
    }
    {   // vB = in_box(cornB, boxA)
        float c = cosf(A[4]), s = sinf(A[4]);
        float lw = __fadd_rn(__fmul_rn(A[2], 0.5f), eps);
        float lh = __fadd_rn(__fmul_rn(A[3], 0.5f), eps);
#pragma unroll
        for (int k = 0; k < 4; k++) {
            float rx = __fsub_rn(bx[k], A[0]), ry = __fsub_rn(by[k], A[1]);
            float xr = __fadd_rn(__fmul_rn(rx, c), __fmul_rn(ry, s));
            float yr = __fadd_rn(__fmul_rn(-rx, s), __fmul_rn(ry, c));
            vl[4+k] = (fabsf(xr) <= lw) && (fabsf(yr) <= lh);
        }
    }
    float dAx[4],dAy[4],dBx[4],dBy[4];
#pragma unroll
    for (int k = 0; k < 4; k++) {
        dAx[k]=__fsub_rn(ax[(k+1)&3],ax[k]); dAy[k]=__fsub_rn(ay[(k+1)&3],ay[k]);
        dBx[k]=__fsub_rn(bx[(k+1)&3],bx[k]); dBy[k]=__fsub_rn(by[(k+1)&3],by[k]);
    }
#pragma unroll
    for (int i = 0; i < 4; i++) {
#pragma unroll
        for (int j = 0; j < 4; j++) {
            float rx  = __fsub_rn(bx[j], ax[i]), ry = __fsub_rn(by[j], ay[i]);
            float den = __fsub_rn(__fmul_rn(dAx[i], dBy[j]), __fmul_rn(dAy[i], dBx[j]));
            float ad  = fabsf(den);
            float dens = (ad < 1e-9f) ? 1.0f : den;
            float t = __fsub_rn(__fmul_rn(rx, dBy[j]), __fmul_rn(ry, dBx[j])) / dens;
            float u = __fsub_rn(__fmul_rn(rx, dAy[i]), __fmul_rn(ry, dAx[i])) / dens;
            bool v  = (ad > 1e-9f) && (t >= -eps) && (t <= ONEPE) && (u >= -eps) && (u <= ONEPE);
            int o = 8 + i*4 + j;
            px[o] = __fadd_rn(ax[i], __fmul_rn(t, dAx[i]));
            py[o] = __fadd_rn(ay[i], __fmul_rn(t, dAy[i]));
            vl[o] = v;
        }
    }
    int cnt = 0;
#pragma unroll
    for (int k = 0; k < 24; k++) cnt += vl[k] ? 1 : 0;
    float sx = 0.0f, sy = 0.0f;
#pragma unroll
    for (int k = 0; k < 24; k++) {
        float f = vl[k] ? 1.0f : 0.0f;
        sx = __fadd_rn(sx, __fmul_rn(px[k], f));
        sy = __fadd_rn(sy, __fmul_rn(py[k], f));
    }
    int cm = cnt > 1 ? cnt : 1;
    float cenx = sx / (float)cm, ceny = sy / (float)cm;
    int am = 0;
#pragma unroll
    for (int k = 23; k >= 0; k--) if (vl[k]) am = k;
    float anx = px[am], anyy = py[am];
    float qx[24], qy[24], ang[24];
#pragma unroll
    for (int k = 0; k < 24; k++) {
        qx[k] = vl[k] ? px[k] : anx;
        qy[k] = vl[k] ? py[k] : anyy;
        ang[k] = atan2f(__fsub_rn(qy[k], ceny), __fsub_rn(qx[k], cenx));
    }
    int ord[24];
    for (int k = 0; k < 24; k++) ord[k] = k;
    for (int k = 1; k < 24; k++) {
        int o = ord[k]; float a = ang[o]; int m = k - 1;
        while (m >= 0 && ang[ord[m]] > a) { ord[m+1] = ord[m]; m--; }
        ord[m+1] = o;
    }
    float ssum = 0.0f;
    for (int k = 0; k < 24; k++) {
        int k0 = ord[k], k1 = ord[(k + 1) % 24];
        float term = __fsub_rn(__fmul_rn(qx[k0], qy[k1]), __fmul_rn(qx[k1], qy[k0]));
        ssum = __fadd_rn(ssum, term);
    }
    float area = __fmul_rn(0.5f, fabsf(ssum));
    return (cnt >= 3) ? area : 0.0f;
}

// ---------------------------------------------------------------- fused: sieve + clips + serial NMS + output (1 block, 256 thr)
// dynamic SMEM layout: [sup: TOPK*32][wl: WCAP_S][aabb: TOPK*4 floats][cls: TOPK ints]
__global__ void __launch_bounds__(256, 1) k_final(float* __restrict__ out) {
    extern __shared__ unsigned s_mem[];
    unsigned* s_sup  = s_mem;                          // 32000 words
    unsigned* s_wl   = s_sup + TOPK*32;                // WCAP_S words
    float*    s_aabb = (float*)(s_wl + WCAP_S);        // TOPK*4 floats
    int*      s_cls  = (int*)(s_aabb + TOPK*4);        // TOPK ints
    __shared__ unsigned keepW[32];
    __shared__ unsigned raW[32];
    __shared__ int s_cc[NCLS];
    __shared__ int s_off[NCLS + 1];
    __shared__ int lst[DETS];
    __shared__ int kcnt;
    __shared__ int wcnt;
    int tid = threadIdx.x;
    int nt  = blockDim.x;

    for (int k = tid; k < TOPK*32; k += nt) s_sup[k] = 0u;
    if (tid < 32) { keepW[tid] = 0u; raW[tid] = 0u; }
    if (tid < NCLS) {
        int n = g_clsCnt[tid];
        s_cc[tid] = (n > CLSCAP) ? CLSCAP : n;
    }
    if (tid == 0) wcnt = 0;
    __syncthreads();
    if (tid == 0) {
        int acc = 0;
        for (int c = 0; c < NCLS; c++) { s_off[c] = acc; acc += s_cc[c]; }
        s_off[NCLS] = acc;
    }
    for (int i = tid; i < TOPK; i += nt) {
        if (g_topVal[i] > neginf()) atomicOr(&keepW[i >> 5], 1u << (i & 31));
        float4 ab = ((const float4*)g_aabb)[i];
        ((float4*)s_aabb)[i] = ab;
    }
    __syncthreads();
    // stage class lists (CSR) into SMEM
    for (int c = 0; c < NCLS; c++) {
        int n = s_cc[c], o = s_off[c];
        for (int k = tid; k < n; k += nt) s_cls[o + k] = g_clsIdx[c*CLSCAP + k];
    }
    __syncthreads();

    // ---- pair sieve, per class, all SMEM ----
    for (int c = 0; c < NCLS; c++) {
        int n = s_cc[c];
        if (n < 2) continue;
        const int* cl = &s_cls[s_off[c]];
        for (int t = tid; t < n*n; t += nt) {
            int i_ = t / n, j_ = t - i_ * n;
            if (i_ >= j_) continue;
            int a = cl[i_], b = cl[j_];
            if (a > b) { int tmp = a; a = b; b = tmp; }
            const float M = 1.0f;
            if (s_aabb[a*4+0] > s_aabb[b*4+1] + M || s_aabb[b*4+0] > s_aabb[a*4+1] + M ||
                s_aabb[a*4+2] > s_aabb[b*4+3] + M || s_aabb[b*4+2] > s_aabb[a*4+3] + M) continue;
            int pos = atomicAdd(&wcnt, 1);
            if (pos < WCAP_S) s_wl[pos] = ((unsigned)a << 16) | (unsigned)b;
        }
    }
    __syncthreads();

    // ---- heavy clips ----
    int W = wcnt; if (W > WCAP_S) W = WCAP_S;
    for (int w = tid; w < W; w += nt) {
        unsigned e = s_wl[w];
        int i = (int)(e >> 16), j = (int)(e & 0xFFFFu);
        float inter = pair_inter_area(&g_nms[i*5], &g_corn[i*8], &g_nms[j*5], &g_corn[j*8]);
        float S   = __fadd_rn(__fsub_rn(__fadd_rn(g_area[i], g_area[j]), inter), 1e-6f);
        float iou = inter / S;
        if (iou > 0.5f) {
            atomicOr(&s_sup[i*32 + (j >> 5)], 1u << (j & 31));
            atomicOr(&raW[i >> 5], 1u << (i & 31));
        }
    }
    __syncthreads();

    // ---- serial NMS over rowAny rows only (warp 0) ----
    if (tid < 32) {
        for (int w = 0; w < 32; w++) {
            unsigned rbits = raW[w];
            while (rbits) {
                int b = __ffs(rbits) - 1;
                rbits &= rbits - 1;
                int i = w * 32 + b;
                if (keepW[w] & (1u << b)) {
                    keepW[tid] &= ~s_sup[i * 32 + tid];
                }
                __syncwarp();
            }
        }
    }
    __syncthreads();

    if (tid == 0) {
        int p = 0;
        for (int w = 0; w < 32 && p < DETS; w++) {
            unsigned m = keepW[w];
            while (m && p < DETS) {
                int b = __ffs(m) - 1;
                m &= m - 1;
                lst[p++] = w * 32 + b;
            }
        }
        kcnt = p;
    }
    __syncthreads();

    for (int r = tid; r < DETS; r += nt) {
        if (r < kcnt) {
            int i = lst[r];
#pragma unroll
            for (int k = 0; k < 5; k++) out[r*5+k] = g_bk[i*5+k];
            out[DETS*5 + r] = (float)g_lab[i];
            out[DETS*6 + r] = g_topVal[i];
        } else {
#pragma unroll
            for (int k = 0; k < 5; k++) out[r*5+k] = 0.0f;
            out[DETS*5 + r] = -1.0f;
            out[DETS*6 + r] = 0.0f;
        }
    }
}

// ---------------------------------------------------------------- launcher
extern "C" void kernel_launch(void* const* d_in, const int* in_sizes, int n_in,
                              void* d_out, int out_size) {
    const float* boxes  = (const float*)d_in[0];
    const float* scores = (const float*)d_in[1];
    const int*   labels = (const int*)d_in[2];
    int n = in_sizes[1];
    int n4 = n / 4;

    static const int FSMEM = (TOPK*32 + WCAP_S + TOPK*4 + TOPK) * (int)sizeof(unsigned);
    cudaFuncSetAttribute(k_final, cudaFuncAttributeMaxDynamicSharedMemorySize, FSMEM);

    k_reset  <<<64, 256>>>();
    k_hist   <<<HIST_GRID, 256>>>((const float4*)scores, n4);
    k_compact<<<1184, 256>>>((const float4*)scores, n4);
    k_selprep<<<SEL_GRID, 256>>>(boxes, labels);
    k_final  <<<1, 256, FSMEM>>>((float*)d_out);
}

// round 7
// speedup vs baseline: 1.1486x; 1.1486x over previous
#include <cuda_runtime.h>
#include <stdint.h>
#include <math.h>

#define TOPK 1000
#define DETS 300
#define NB    4608          // bins over (0.05, 1.0] via fb>>13 - BASE
#define CH    18            // NB / 256
#define BASE  125542        // 0x3D4CCCCD >> 13  (0.05f)
#define CAND_CAP 32768
#define SELCAP   6144
#define NCLS  80
#define CLSCAP 1024
#define WCAP_S 4096
#define FAST_T 0.999f

#define HIST_GRID 148
#define CMP_GRID  592
#define SEL_GRID  128

__device__ unsigned int       g_hist1[NB];
__device__ unsigned int       g_sel[8];     // [0]=B1 [2]=cand cnt [3]=skip-compact flag [6]=hist ticket [7]=sel ticket
__device__ unsigned long long g_cand[CAND_CAP];
__device__ int                g_topIdx[TOPK];
__device__ float              g_topVal[TOPK];
__device__ float              g_bk[TOPK*5];      // original boxes (output)
__device__ float              g_nms[TOPK*5];     // offset boxes (NMS domain)
__device__ float              g_corn[TOPK*8];
__device__ float              g_aabb[TOPK*4];    // minx,maxx,miny,maxy
__device__ float              g_area[TOPK];
__device__ int                g_clsCnt[NCLS];
__device__ int                g_clsIdx[NCLS*CLSCAP];
__device__ int                g_lab[TOPK];

__device__ __forceinline__ float neginf() { return __int_as_float(0xff800000); }

__device__ __forceinline__ int bin_of(unsigned fb) {
    int b = (int)(fb >> 13) - BASE;
    if (b < 0) b = 0;
    if (b > NB - 1) b = NB - 1;
    return b;
}

// ---------------------------------------------------------------- pass 1: histogram + opportunistic compact + fused findb1
__global__ void k_hist(const float4* __restrict__ sc4, int n4) {
    __shared__ unsigned int h[NB];
    __shared__ unsigned csum[256];
    __shared__ int isLast;
    int tid = threadIdx.x;
    for (int k = tid; k < NB; k += blockDim.x) h[k] = 0;
    __syncthreads();
    int i0 = blockIdx.x * blockDim.x + tid;
    int S  = gridDim.x * blockDim.x;
    for (int p = i0; p < n4; p += 4 * S) {
        int p1 = p + S, p2 = p + 2*S, p3 = p + 3*S;
        float4 v0 = sc4[p];
        float4 v1 = (p1 < n4) ? sc4[p1] : make_float4(0,0,0,0);
        float4 v2 = (p2 < n4) ? sc4[p2] : make_float4(0,0,0,0);
        float4 v3 = (p3 < n4) ? sc4[p3] : make_float4(0,0,0,0);
        float vs[16] = { v0.x,v0.y,v0.z,v0.w, v1.x,v1.y,v1.z,v1.w,
                         v2.x,v2.y,v2.z,v2.w, v3.x,v3.y,v3.z,v3.w };
        int  pq[4] = { p, p1, p2, p3 };
#pragma unroll
        for (int l = 0; l < 16; l++) {
            float s = vs[l];
            if (s > 0.05f) {
                unsigned fb = __float_as_uint(s);
                atomicAdd(&h[bin_of(fb)], 1u);
                if (s > FAST_T) {   // opportunistic compact
                    unsigned pos = atomicAdd(&g_sel[2], 1u);
                    if (pos < CAND_CAP) {
                        unsigned idx = (unsigned)(pq[l >> 2] * 4 + (l & 3));
                        g_cand[pos] = ((unsigned long long)fb << 32) |
                                      (unsigned long long)(0xFFFFFFFFu - idx);
                    }
                }
            }
        }
    }
    __syncthreads();
    for (int k = tid; k < NB; k += blockDim.x) {
        unsigned v = h[k];
        if (v) atomicAdd(&g_hist1[k], v);
    }
    __threadfence();
    if (tid == 0) {
        unsigned t = atomicAdd(&g_sel[6], 1u);
        isLast = (t == gridDim.x - 1);
    }
    __syncthreads();
    if (!isLast) return;
    __threadfence();
    // ---- fused findb1 + self-clean ----
    for (int k = tid; k < NB; k += blockDim.x) { h[k] = g_hist1[k]; g_hist1[k] = 0; }
    __syncthreads();
    unsigned s = 0;
    for (int b = tid * CH; b < tid * CH + CH; b++) s += h[b];
    csum[tid] = s;
    __syncthreads();
    if (tid == 0) {
        unsigned cum = 0; int B1 = -1;
        for (int c = 255; c >= 0; c--) {
            if (cum + csum[c] >= TOPK) {
                for (int b = c * CH + CH - 1; b >= c * CH; b--) {
                    if (cum + h[b] >= TOPK) { B1 = b; break; }
                    cum += h[b];
                }
                break;
            }
            cum += csum[c];
        }
        if (B1 < 0) B1 = 0;
        g_sel[0] = (unsigned)B1;
        g_sel[6] = 0;                                  // reset ticket
        unsigned ct = g_sel[2];
        int skip = (ct >= TOPK && ct <= CAND_CAP) ? 1 : 0;
        g_sel[3] = (unsigned)skip;
        if (!skip) g_sel[2] = 0;                       // compact pass rebuilds
    }
}

// ---------------------------------------------------------------- pass 2 (fallback only): compact (bin >= B1)
__global__ void k_compact(const float4* __restrict__ sc4, int n4) {
    if (g_sel[3]) return;                              // fast path: already have candidates
    unsigned B1 = g_sel[0];
    int i0 = blockIdx.x * blockDim.x + threadIdx.x;
    int S  = gridDim.x * blockDim.x;
    for (int p = i0; p < n4; p += 2 * S) {
        int p1 = p + S;
        float4 v0 = sc4[p];
        float4 v1 = (p1 < n4) ? sc4[p1] : make_float4(0,0,0,0);
        float vs[8] = { v0.x,v0.y,v0.z,v0.w, v1.x,v1.y,v1.z,v1.w };
        int   pb[2] = { p, p1 };
#pragma unroll
        for (int l = 0; l < 8; l++) {
            float s = vs[l];
            if (s > 0.05f) {
                unsigned fb = __float_as_uint(s);
                if (bin_of(fb) >= (int)B1) {
                    unsigned pos = atomicAdd(&g_sel[2], 1u);
                    if (pos < CAND_CAP) {
                        unsigned idx = (unsigned)(pb[l >> 2] * 4 + (l & 3));
                        g_cand[pos] = ((unsigned long long)fb << 32) |
                                      (unsigned long long)(0xFFFFFFFFu - idx);
                    }
                }
            }
        }
    }
}

// ---------------------------------------------------------------- select: 16-lane cooperative rank + fused prep (last block)
__global__ void k_selprep(const float* __restrict__ boxes, const int* __restrict__ labels) {
    __shared__ unsigned long long sk[SELCAP];
    __shared__ int isLast;
    unsigned C = g_sel[2];
    if (C > CAND_CAP) C = CAND_CAP;
    int tid = threadIdx.x;
    bool small = (C <= SELCAP);
    const unsigned long long* base;
    if (small) {
        for (unsigned k = (unsigned)tid; k < C; k += blockDim.x) sk[k] = g_cand[k];
        base = sk;
    } else {
        base = g_cand;
    }
    __syncthreads();

    unsigned lane  = (unsigned)tid & 15u;
    unsigned gidx  = (unsigned)(blockIdx.x * blockDim.x + tid) >> 4;
    unsigned cstr  = (unsigned)(gridDim.x * blockDim.x) >> 4;
    unsigned nIter = (C + cstr - 1) / cstr;
    for (unsigned it = 0; it < nIter; it++) {
        unsigned c = gidx + it * cstr;
        bool act = (c < C);
        unsigned long long key = act ? base[c] : 0ULL;
        unsigned rank = 0;
        unsigned k = lane;
        for (; k + 48 < C; k += 64) {                  // MLP=4, 16-lane stride
            unsigned long long a0 = base[k], a1 = base[k+16], a2 = base[k+32], a3 = base[k+48];
            rank += (a0 > key) + (a1 > key) + (a2 > key) + (a3 > key);
        }
        for (; k < C; k += 16) rank += (base[k] > key) ? 1u : 0u;
        rank += __shfl_down_sync(0xffffffffu, rank, 8, 16);
        rank += __shfl_down_sync(0xffffffffu, rank, 4, 16);
        rank += __shfl_down_sync(0xffffffffu, rank, 2, 16);
        rank += __shfl_down_sync(0xffffffffu, rank, 1, 16);
        if (act && lane == 0 && rank < TOPK) {
            g_topIdx[rank] = (int)(0xFFFFFFFFu - (unsigned)(key & 0xFFFFFFFFull));
            g_topVal[rank] = __uint_as_float((unsigned)(key >> 32));
        }
    }
    __threadfence();
    __syncthreads();
    if (tid == 0) {
        unsigned t = atomicAdd(&g_sel[7], 1u);
        isLast = (t == gridDim.x - 1);
    }
    __syncthreads();
    if (!isLast) return;
    __threadfence();
    // ---- fused prep: gather + offset + corners + AABB + class lists ----
    for (int i = tid; i < TOPK; i += blockDim.x) {
        int idx = g_topIdx[i];
        if (idx < 0) { g_lab[i] = -2 - i; g_area[i] = 0.0f; continue; }
        float cx = boxes[idx*5+0], cy = boxes[idx*5+1];
        float w  = boxes[idx*5+2], h  = boxes[idx*5+3];
        float a  = boxes[idx*5+4];
        g_bk[i*5+0]=cx; g_bk[i*5+1]=cy; g_bk[i*5+2]=w; g_bk[i*5+3]=h; g_bk[i*5+4]=a;
        int lab = labels[idx];
        g_lab[i] = lab;
        float off = __fmul_rn((float)lab, 10000.0f);
        float cxo = __fadd_rn(cx, off);
        float cyo = __fadd_rn(cy, off);
        g_nms[i*5+0]=cxo; g_nms[i*5+1]=cyo; g_nms[i*5+2]=w; g_nms[i*5+3]=h; g_nms[i*5+4]=a;
        g_area[i] = __fmul_rn(w, h);

        float c = cosf(a), s = sinf(a);
        float dx = __fmul_rn(w, 0.5f), dy = __fmul_rn(h, 0.5f);
        float ox[4] = { dx, -dx, -dx,  dx };
        float oy[4] = { dy,  dy, -dy, -dy };
        float mnx =  3.4e38f, mxx = -3.4e38f, mny = 3.4e38f, mxy = -3.4e38f;
#pragma unroll
        for (int j = 0; j < 4; j++) {
            float x = __fsub_rn(__fadd_rn(cxo, __fmul_rn(ox[j], c)), __fmul_rn(oy[j], s));
            float y = __fadd_rn(__fadd_rn(cyo, __fmul_rn(ox[j], s)), __fmul_rn(oy[j], c));
            g_corn[i*8 + 2*j]     = x;
            g_corn[i*8 + 2*j + 1] = y;
            mnx = fminf(mnx, x); mxx = fmaxf(mxx, x);
            mny = fminf(mny, y); mxy = fmaxf(mxy, y);
        }
        g_aabb[i*4+0]=mnx; g_aabb[i*4+1]=mxx; g_aabb[i*4+2]=mny; g_aabb[i*4+3]=mxy;
        if (lab >= 0 && lab < NCLS) {
            int pos = atomicAdd(&g_clsCnt[lab], 1);
            if (pos < CLSCAP) g_clsIdx[lab*CLSCAP + pos] = i;
        }
    }
    // self-clean for next call
    if (tid == 0) { g_sel[7] = 0; g_sel[2] = 0; g_sel[3] = 0; }
}

// ---------------------------------------------------------------- exact replica of _pair_inter_area (fp32, no FMA, seq order)
__device__ float pair_inter_area(const float* A, const float* cA,
                                 const float* B, const float* cB) {
    const float eps = 1e-6f;
    const float ONEPE = 1.000001f;
    float px[24], py[24];
    bool  vl[24];
    float ax[4], ay[4], bx[4], by[4];
#pragma unroll
    for (int k = 0; k < 4; k++) {
        ax[k]=cA[2*k]; ay[k]=cA[2*k+1]; bx[k]=cB[2*k]; by[k]=cB[2*k+1];
        px[k]=ax[k]; py[k]=ay[k]; px[4+k]=bx[k]; py[4+k]=by[k];
    }
    {   // vA = in_box(cornA, boxB)
        float c = cosf(B[4]), s = sinf(B[4]);
        float lw = __fadd_rn(__fmul_rn(B[2], 0.5f), eps);
        float lh = __fadd_rn(__fmul_rn(B[3], 0.5f), eps);
#pragma unroll
        for (int k = 0; k < 4; k++) {
            float rx = __fsub_rn(ax[k], B[0]), ry = __fsub_rn(ay[k], B[1]);
            float xr = __fadd_rn(__fmul_rn(rx, c), __fmul_rn(ry, s));
            float yr = __fadd_rn(__fmul_rn(-rx, s), __fmul_rn(ry, c));
            vl[k] = (fabsf(xr) <= lw) && (fabsf(yr) <= lh);
        }
    }
    {   // vB = in_box(cornB, boxA)
        float c = cosf(A[4]), s = sinf(A[4]);
        float lw = __fadd_rn(__fmul_rn(A[2], 0.5f), eps);
        float lh = __fadd_rn(__fmul_rn(A[3], 0.5f), eps);
#pragma unroll
        for (int k = 0; k < 4; k++) {
            float rx = __fsub_rn(bx[k], A[0]), ry = __fsub_rn(by[k], A[1]);
            float xr = __fadd_rn(__fmul_rn(rx, c), __fmul_rn(ry, s));
            float yr = __fadd_rn(__fmul_rn(-rx, s), __fmul_rn(ry, c));
            vl[4+k] = (fabsf(xr) <= lw) && (fabsf(yr) <= lh);
        }
    }
    float dAx[4],dAy[4],dBx[4],dBy[4];
#pragma unroll
    for (int k = 0; k < 4; k++) {
        dAx[k]=__fsub_rn(ax[(k+1)&3],ax[k]); dAy[k]=__fsub_rn(ay[(k+1)&3],ay[k]);
        dBx[k]=__fsub_rn(bx[(k+1)&3],bx[k]); dBy[k]=__fsub_rn(by[(k+1)&3],by[k]);
    }
#pragma unroll
    for (int i = 0; i < 4; i++) {
#pragma unroll
        for (int j = 0; j < 4; j++) {
            float rx  = __fsub_rn(bx[j], ax[i]), ry = __fsub_rn(by[j], ay[i]);
            float den = __fsub_rn(__fmul_rn(dAx[i], dBy[j]), __fmul_rn(dAy[i], dBx[j]));
            float ad  = fabsf(den);
            float dens = (ad < 1e-9f) ? 1.0f : den;
            float t = __fsub_rn(__fmul_rn(rx, dBy[j]), __fmul_rn(ry, dBx[j])) / dens;
            float u = __fsub_rn(__fmul_rn(rx, dAy[i]), __fmul_rn(ry, dAx[i])) / dens;
            bool v  = (ad > 1e-9f) && (t >= -eps) && (t <= ONEPE) && (u >= -eps) && (u <= ONEPE);
            int o = 8 + i*4 + j;
            px[o] = __fadd_rn(ax[i], __fmul_rn(t, dAx[i]));
            py[o] = __fadd_rn(ay[i], __fmul_rn(t, dAy[i]));
            vl[o] = v;
        }
    }
    int cnt = 0;
#pragma unroll
    for (int k = 0; k < 24; k++) cnt += vl[k] ? 1 : 0;
    float sx = 0.0f, sy = 0.0f;
#pragma unroll
    for (int k = 0; k < 24; k++) {
        float f = vl[k] ? 1.0f : 0.0f;
        sx = __fadd_rn(sx, __fmul_rn(px[k], f));
        sy = __fadd_rn(sy, __fmul_rn(py[k], f));
    }
    int cm = cnt > 1 ? cnt : 1;
    float cenx = sx / (float)cm, ceny = sy / (float)cm;
    int am = 0;
#pragma unroll
    for (int k = 23; k >= 0; k--) if (vl[k]) am = k;
    float anx = px[am], anyy = py[am];
    float qx[24], qy[24], ang[24];
#pragma unroll
    for (int k = 0; k < 24; k++) {
        qx[k] = vl[k] ? px[k] : anx;
        qy[k] = vl[k] ? py[k] : anyy;
        ang[k] = atan2f(__fsub_rn(qy[k], ceny), __fsub_rn(qx[k], cenx));
    }
    int ord[24];
    for (int k = 0; k < 24; k++) ord[k] = k;
    for (int k = 1; k < 24; k++) {
        int o = ord[k]; float a = ang[o]; int m = k - 1;
        while (m >= 0 && ang[ord[m]] > a) { ord[m+1] = ord[m]; m--; }
        ord[m+1] = o;
    }
    float ssum = 0.0f;
    for (int k = 0; k < 24; k++) {
        int k0 = ord[k], k1 = ord[(k + 1) % 24];
        float term = __fsub_rn(__fmul_rn(qx[k0], qy[k1]), __fmul_rn(qx[k1], qy[k0]));
        ssum = __fadd_rn(ssum, term);
    }
    float area = __fmul_rn(0.5f, fabsf(ssum));
    return (cnt >= 3) ? area : 0.0f;
}

// ---------------------------------------------------------------- fused: sieve + clips + serial NMS + output (1 block, 256 thr)
__global__ void __launch_bounds__(256, 1) k_final(float* __restrict__ out) {
    extern __shared__ unsigned s_mem[];
    unsigned* s_sup  = s_mem;                          // 32000 words
    unsigned* s_wl   = s_sup + TOPK*32;                // WCAP_S words
    float*    s_aabb = (float*)(s_wl + WCAP_S);        // TOPK*4 floats
    int*      s_cls  = (int*)(s_aabb + TOPK*4);        // TOPK ints
    __shared__ unsigned keepW[32];
    __shared__ unsigned raW[32];
    __shared__ int s_cc[NCLS];
    __shared__ int s_off[NCLS + 1];
    __shared__ int lst[DETS];
    __shared__ int kcnt;
    __shared__ int wcnt;
    int tid = threadIdx.x;
    int nt  = blockDim.x;

    for (int k = tid; k < TOPK*32; k += nt) s_sup[k] = 0u;
    if (tid < 32) { keepW[tid] = 0u; raW[tid] = 0u; }
    if (tid < NCLS) {
        int n = g_clsCnt[tid];
        s_cc[tid] = (n > CLSCAP) ? CLSCAP : n;
        g_clsCnt[tid] = 0;                             // self-clean for next call
    }
    if (tid == 0) wcnt = 0;
    __syncthreads();
    if (tid == 0) {
        int acc = 0;
        for (int c = 0; c < NCLS; c++) { s_off[c] = acc; acc += s_cc[c]; }
        s_off[NCLS] = acc;
    }
    for (int i = tid; i < TOPK; i += nt) {
        if (g_topVal[i] > neginf()) atomicOr(&keepW[i >> 5], 1u << (i & 31));
        float4 ab = ((const float4*)g_aabb)[i];
        ((float4*)s_aabb)[i] = ab;
    }
    __syncthreads();
    // stage class lists (CSR) into SMEM
    for (int c = 0; c < NCLS; c++) {
        int n = s_cc[c], o = s_off[c];
        for (int k = tid; k < n; k += nt) s_cls[o + k] = g_clsIdx[c*CLSCAP + k];
    }
    __syncthreads();

    // ---- pair sieve, per class, all SMEM ----
    for (int c = 0; c < NCLS; c++) {
        int n = s_cc[c];
        if (n < 2) continue;
        const int* cl = &s_cls[s_off[c]];
        for (int t = tid; t < n*n; t += nt) {
            int i_ = t / n, j_ = t - i_ * n;
            if (i_ >= j_) continue;
            int a = cl[i_], b = cl[j_];
            if (a > b) { int tmp = a; a = b; b = tmp; }
            const float M = 1.0f;
            if (s_aabb[a*4+0] > s_aabb[b*4+1] + M || s_aabb[b*4+0] > s_aabb[a*4+1] + M ||
                s_aabb[a*4+2] > s_aabb[b*4+3] + M || s_aabb[b*4+2] > s_aabb[a*4+3] + M) continue;
            int pos = atomicAdd(&wcnt, 1);
            if (pos < WCAP_S) s_wl[pos] = ((unsigned)a << 16) | (unsigned)b;
        }
    }
    __syncthreads();

    // ---- heavy clips ----
    int W = wcnt; if (W > WCAP_S) W = WCAP_S;
    for (int w = tid; w < W; w += nt) {
        unsigned e = s_wl[w];
        int i = (int)(e >> 16), j = (int)(e & 0xFFFFu);
        float inter = pair_inter_area(&g_nms[i*5], &g_corn[i*8], &g_nms[j*5], &g_corn[j*8]);
        float S   = __fadd_rn(__fsub_rn(__fadd_rn(g_area[i], g_area[j]), inter), 1e-6f);
        float iou = inter / S;
        if (iou > 0.5f) {
            atomicOr(&s_sup[i*32 + (j >> 5)], 1u << (j & 31));
            atomicOr(&raW[i >> 5], 1u << (i & 31));
        }
    }
    __syncthreads();

    // ---- serial NMS over rowAny rows only (warp 0) ----
    if (tid < 32) {
        for (int w = 0; w < 32; w++) {
            unsigned rbits = raW[w];
            while (rbits) {
                int b = __ffs(rbits) - 1;
                rbits &= rbits - 1;
                int i = w * 32 + b;
                if (keepW[w] & (1u << b)) {
                    keepW[tid] &= ~s_sup[i * 32 + tid];
                }
                __syncwarp();
            }
        }
    }
    __syncthreads();

    if (tid == 0) {
        int p = 0;
        for (int w = 0; w < 32 && p < DETS; w++) {
            unsigned m = keepW[w];
            while (m && p < DETS) {
                int b = __ffs(m) - 1;
                m &= m - 1;
                lst[p++] = w * 32 + b;
            }
        }
        kcnt = p;
    }
    __syncthreads();

    for (int r = tid; r < DETS; r += nt) {
        if (r < kcnt) {
            int i = lst[r];
#pragma unroll
            for (int k = 0; k < 5; k++) out[r*5+k] = g_bk[i*5+k];
            out[DETS*5 + r] = (float)g_lab[i];
            out[DETS*6 + r] = g_topVal[i];
        } else {
#pragma unroll
            for (int k = 0; k < 5; k++) out[r*5+k] = 0.0f;
            out[DETS*5 + r] = -1.0f;
            out[DETS*6 + r] = 0.0f;
        }
    }
}

// ---------------------------------------------------------------- launcher
extern "C" void kernel_launch(void* const* d_in, const int* in_sizes, int n_in,
                              void* d_out, int out_size) {
    const float* boxes  = (const float*)d_in[0];
    const float* scores = (const float*)d_in[1];
    const int*   labels = (const int*)d_in[2];
    int n = in_sizes[1];
    int n4 = n / 4;

    static const int FSMEM = (TOPK*32 + WCAP_S + TOPK*4 + TOPK) * (int)sizeof(unsigned);
    cudaFuncSetAttribute(k_final, cudaFuncAttributeMaxDynamicSharedMemorySize, FSMEM);

    k_hist   <<<HIST_GRID, 256>>>((const float4*)scores, n4);
    k_compact<<<CMP_GRID, 256>>>((const float4*)scores, n4);
    k_selprep<<<SEL_GRID, 256>>>(boxes, labels);
    k_final  <<<1, 256, FSMEM>>>((float*)d_out);
}

// round 8
// speedup vs baseline: 1.3959x; 1.2154x over previous
#include <cuda_runtime.h>
#include <stdint.h>
#include <math.h>

#define TOPK 1000
#define DETS 300
#define NB    4608          // bins over (0.05, 1.0] via fb>>13 - BASE
#define CH    18            // NB / 256
#define BASE  125542        // 0x3D4CCCCD >> 13  (0.05f)
#define CAND_CAP 32768
#define SELCAP   6144
#define NCLS  80
#define WCAP  8192
#define SPCAP 8192
#define FAST_T 0.999f

#define HIST_GRID 148
#define CMP_GRID  592
#define SEL_GRID  128

__device__ unsigned int       g_hist1[NB];
__device__ unsigned int       g_sel[8];     // [0]=B1 [2]=cand cnt [3]=skip flag [4]=work cnt [5]=sup-pair cnt [6]=hist ticket [7]=sel ticket
__device__ unsigned long long g_cand[CAND_CAP];
__device__ unsigned int       g_work[WCAP];
__device__ unsigned int       g_supPairs[SPCAP];
__device__ int                g_topIdx[TOPK];
__device__ float              g_topVal[TOPK];
__device__ float              g_bk[TOPK*5];      // original boxes (output)
__device__ float              g_nms[TOPK*5];     // offset boxes (NMS domain)
__device__ float              g_corn[TOPK*8];
__device__ float              g_aabb[TOPK*4];    // minx,maxx,miny,maxy
__device__ float              g_area[TOPK];
__device__ int                g_lab[TOPK];

__device__ __forceinline__ float neginf() { return __int_as_float(0xff800000); }

__device__ __forceinline__ int bin_of(unsigned fb) {
    int b = (int)(fb >> 13) - BASE;
    if (b < 0) b = 0;
    if (b > NB - 1) b = NB - 1;
    return b;
}

// ---------------------------------------------------------------- pass 1: histogram + opportunistic compact + fused findb1
__global__ void k_hist(const float4* __restrict__ sc4, int n4) {
    __shared__ unsigned int h[NB];
    __shared__ unsigned csum[256];
    __shared__ int isLast;
    int tid = threadIdx.x;
    for (int k = tid; k < NB; k += blockDim.x) h[k] = 0;
    __syncthreads();
    int i0 = blockIdx.x * blockDim.x + tid;
    int S  = gridDim.x * blockDim.x;
    for (int p = i0; p < n4; p += 4 * S) {
        int p1 = p + S, p2 = p + 2*S, p3 = p + 3*S;
        float4 v0 = sc4[p];
        float4 v1 = (p1 < n4) ? sc4[p1] : make_float4(0,0,0,0);
        float4 v2 = (p2 < n4) ? sc4[p2] : make_float4(0,0,0,0);
        float4 v3 = (p3 < n4) ? sc4[p3] : make_float4(0,0,0,0);
        float vs[16] = { v0.x,v0.y,v0.z,v0.w, v1.x,v1.y,v1.z,v1.w,
                         v2.x,v2.y,v2.z,v2.w, v3.x,v3.y,v3.z,v3.w };
        int  pq[4] = { p, p1, p2, p3 };
#pragma unroll
        for (int l = 0; l < 16; l++) {
            float s = vs[l];
            if (s > 0.05f) {
                unsigned fb = __float_as_uint(s);
                atomicAdd(&h[bin_of(fb)], 1u);
                if (s > FAST_T) {   // opportunistic compact
                    unsigned pos = atomicAdd(&g_sel[2], 1u);
                    if (pos < CAND_CAP) {
                        unsigned idx = (unsigned)(pq[l >> 2] * 4 + (l & 3));
                        g_cand[pos] = ((unsigned long long)fb << 32) |
                                      (unsigned long long)(0xFFFFFFFFu - idx);
                    }
                }
            }
        }
    }
    __syncthreads();
    for (int k = tid; k < NB; k += blockDim.x) {
        unsigned v = h[k];
        if (v) atomicAdd(&g_hist1[k], v);
    }
    __threadfence();
    if (tid == 0) {
        unsigned t = atomicAdd(&g_sel[6], 1u);
        isLast = (t == gridDim.x - 1);
    }
    __syncthreads();
    if (!isLast) return;
    __threadfence();
    // ---- fused findb1 + self-clean ----
    for (int k = tid; k < NB; k += blockDim.x) { h[k] = g_hist1[k]; g_hist1[k] = 0; }
    __syncthreads();
    unsigned s = 0;
    for (int b = tid * CH; b < tid * CH + CH; b++) s += h[b];
    csum[tid] = s;
    __syncthreads();
    if (tid == 0) {
        unsigned cum = 0; int B1 = -1;
        for (int c = 255; c >= 0; c--) {
            if (cum + csum[c] >= TOPK) {
                for (int b = c * CH + CH - 1; b >= c * CH; b--) {
                    if (cum + h[b] >= TOPK) { B1 = b; break; }
                    cum += h[b];
                }
                break;
            }
            cum += csum[c];
        }
        if (B1 < 0) B1 = 0;
        g_sel[0] = (unsigned)B1;
        g_sel[6] = 0;                                  // reset ticket
        unsigned ct = g_sel[2];
        int skip = (ct >= TOPK && ct <= CAND_CAP) ? 1 : 0;
        g_sel[3] = (unsigned)skip;
        if (!skip) g_sel[2] = 0;                       // compact pass rebuilds
    }
}

// ---------------------------------------------------------------- pass 2 (fallback only): compact (bin >= B1)
__global__ void k_compact(const float4* __restrict__ sc4, int n4) {
    if (g_sel[3]) return;                              // fast path: already have candidates
    unsigned B1 = g_sel[0];
    int i0 = blockIdx.x * blockDim.x + threadIdx.x;
    int S  = gridDim.x * blockDim.x;
    for (int p = i0; p < n4; p += 2 * S) {
        int p1 = p + S;
        float4 v0 = sc4[p];
        float4 v1 = (p1 < n4) ? sc4[p1] : make_float4(0,0,0,0);
        float vs[8] = { v0.x,v0.y,v0.z,v0.w, v1.x,v1.y,v1.z,v1.w };
        int   pb[2] = { p, p1 };
#pragma unroll
        for (int l = 0; l < 8; l++) {
            float s = vs[l];
            if (s > 0.05f) {
                unsigned fb = __float_as_uint(s);
                if (bin_of(fb) >= (int)B1) {
                    unsigned pos = atomicAdd(&g_sel[2], 1u);
                    if (pos < CAND_CAP) {
                        unsigned idx = (unsigned)(pb[l >> 2] * 4 + (l & 3));
                        g_cand[pos] = ((unsigned long long)fb << 32) |
                                      (unsigned long long)(0xFFFFFFFFu - idx);
                    }
                }
            }
        }
    }
}

// ---------------------------------------------------------------- select (16-lane rank) + fused prep + AABB sieve (last block)
__global__ void k_selprep(const float* __restrict__ boxes, const int* __restrict__ labels) {
    __shared__ unsigned long long sk[SELCAP];
    __shared__ int isLast;
    __shared__ int s_cc[NCLS];
    __shared__ int s_off[NCLS + 1];
    __shared__ int s_fill[NCLS];
    unsigned C = g_sel[2];
    if (C > CAND_CAP) C = CAND_CAP;
    int tid = threadIdx.x;
    bool small = (C <= SELCAP);
    const unsigned long long* base;
    if (small) {
        for (unsigned k = (unsigned)tid; k < C; k += blockDim.x) sk[k] = g_cand[k];
        base = sk;
    } else {
        base = g_cand;
    }
    __syncthreads();

    unsigned lane  = (unsigned)tid & 15u;
    unsigned gidx  = (unsigned)(blockIdx.x * blockDim.x + tid) >> 4;
    unsigned cstr  = (unsigned)(gridDim.x * blockDim.x) >> 4;
    unsigned nIter = (C + cstr - 1) / cstr;
    for (unsigned it = 0; it < nIter; it++) {
        unsigned c = gidx + it * cstr;
        bool act = (c < C);
        unsigned long long key = act ? base[c] : 0ULL;
        unsigned rank = 0;
        unsigned k = lane;
        for (; k + 48 < C; k += 64) {
            unsigned long long a0 = base[k], a1 = base[k+16], a2 = base[k+32], a3 = base[k+48];
            rank += (a0 > key) + (a1 > key) + (a2 > key) + (a3 > key);
        }
        for (; k < C; k += 16) rank += (base[k] > key) ? 1u : 0u;
        rank += __shfl_down_sync(0xffffffffu, rank, 8, 16);
        rank += __shfl_down_sync(0xffffffffu, rank, 4, 16);
        rank += __shfl_down_sync(0xffffffffu, rank, 2, 16);
        rank += __shfl_down_sync(0xffffffffu, rank, 1, 16);
        if (act && lane == 0 && rank < TOPK) {
            g_topIdx[rank] = (int)(0xFFFFFFFFu - (unsigned)(key & 0xFFFFFFFFull));
            g_topVal[rank] = __uint_as_float((unsigned)(key >> 32));
        }
    }
    __threadfence();
    __syncthreads();
    if (tid == 0) {
        unsigned t = atomicAdd(&g_sel[7], 1u);
        isLast = (t == gridDim.x - 1);
    }
    __syncthreads();
    if (!isLast) return;
    __threadfence();

    // ---- fused prep: gather + offset + corners + AABB ----
    if (tid < NCLS) { s_cc[tid] = 0; s_fill[tid] = 0; }
    if (tid == 0) { g_sel[4] = 0; g_sel[5] = 0; g_sel[7] = 0; g_sel[2] = 0; g_sel[3] = 0; }
    __syncthreads();
    for (int i = tid; i < TOPK; i += blockDim.x) {
        int idx = g_topIdx[i];
        if (idx < 0) { g_lab[i] = -1 - NCLS; g_area[i] = 0.0f; continue; }
        float cx = boxes[idx*5+0], cy = boxes[idx*5+1];
        float w  = boxes[idx*5+2], h  = boxes[idx*5+3];
        float a  = boxes[idx*5+4];
        g_bk[i*5+0]=cx; g_bk[i*5+1]=cy; g_bk[i*5+2]=w; g_bk[i*5+3]=h; g_bk[i*5+4]=a;
        int lab = labels[idx];
        g_lab[i] = lab;
        float off = __fmul_rn((float)lab, 10000.0f);
        float cxo = __fadd_rn(cx, off);
        float cyo = __fadd_rn(cy, off);
        g_nms[i*5+0]=cxo; g_nms[i*5+1]=cyo; g_nms[i*5+2]=w; g_nms[i*5+3]=h; g_nms[i*5+4]=a;
        g_area[i] = __fmul_rn(w, h);

        float c = cosf(a), s = sinf(a);
        float dx = __fmul_rn(w, 0.5f), dy = __fmul_rn(h, 0.5f);
        float ox[4] = { dx, -dx, -dx,  dx };
        float oy[4] = { dy,  dy, -dy, -dy };
        float mnx =  3.4e38f, mxx = -3.4e38f, mny = 3.4e38f, mxy = -3.4e38f;
#pragma unroll
        for (int j = 0; j < 4; j++) {
            float x = __fsub_rn(__fadd_rn(cxo, __fmul_rn(ox[j], c)), __fmul_rn(oy[j], s));
            float y = __fadd_rn(__fadd_rn(cyo, __fmul_rn(ox[j], s)), __fmul_rn(oy[j], c));
            g_corn[i*8 + 2*j]     = x;
            g_corn[i*8 + 2*j + 1] = y;
            mnx = fminf(mnx, x); mxx = fmaxf(mxx, x);
            mny = fminf(mny, y); mxy = fmaxf(mxy, y);
        }
        g_aabb[i*4+0]=mnx; g_aabb[i*4+1]=mxx; g_aabb[i*4+2]=mny; g_aabb[i*4+3]=mxy;
        if (lab >= 0 && lab < NCLS) atomicAdd(&s_cc[lab], 1);
    }
    __syncthreads();

    // ---- class CSR + stage AABBs into sk space ----
    float* s_aabb = (float*)sk;                 // 4000 floats (16KB)  — sk dead now
    int*   s_cls  = (int*)(s_aabb + TOPK*4);    // 1000 ints
    if (tid == 0) {
        int acc = 0;
        for (int c = 0; c < NCLS; c++) { s_off[c] = acc; acc += s_cc[c]; }
        s_off[NCLS] = acc;
    }
    __syncthreads();
    for (int i = tid; i < TOPK; i += blockDim.x) {
        ((float4*)s_aabb)[i] = ((const float4*)g_aabb)[i];
        int lab = g_lab[i];
        if (lab >= 0 && lab < NCLS) {
            int pos = atomicAdd(&s_fill[lab], 1);
            s_cls[s_off[lab] + pos] = i;
        }
    }
    __syncthreads();

    // ---- AABB sieve -> global worklist ----
    for (int c = 0; c < NCLS; c++) {
        int n = s_cc[c];
        if (n < 2) continue;
        const int* cl = &s_cls[s_off[c]];
        for (int t = tid; t < n*n; t += blockDim.x) {
            int i_ = t / n, j_ = t - i_ * n;
            if (i_ >= j_) continue;
            int a = cl[i_], b = cl[j_];
            if (a > b) { int tmp = a; a = b; b = tmp; }
            const float M = 1.0f;
            if (s_aabb[a*4+0] > s_aabb[b*4+1] + M || s_aabb[b*4+0] > s_aabb[a*4+1] + M ||
                s_aabb[a*4+2] > s_aabb[b*4+3] + M || s_aabb[b*4+2] > s_aabb[a*4+3] + M) continue;
            unsigned pos = atomicAdd(&g_sel[4], 1u);
            if (pos < WCAP) g_work[pos] = ((unsigned)a << 16) | (unsigned)b;
        }
    }
}

// ---------------------------------------------------------------- exact replica of _pair_inter_area (fp32, no FMA, seq order)
__device__ float pair_inter_area(const float* A, const float* cA,
                                 const float* B, const float* cB) {
    const float eps = 1e-6f;
    const float ONEPE = 1.000001f;
    float px[24], py[24];
    bool  vl[24];
    float ax[4], ay[4], bx[4], by[4];
#pragma unroll
    for (int k = 0; k < 4; k++) {
        ax[k]=cA[2*k]; ay[k]=cA[2*k+1]; bx[k]=cB[2*k]; by[k]=cB[2*k+1];
        px[k]=ax[k]; py[k]=ay[k]; px[4+k]=bx[k]; py[4+k]=by[k];
    }
    {   // vA = in_box(cornA, boxB)
        float c = cosf(B[4]), s = sinf(B[4]);
        float lw = __fadd_rn(__fmul_rn(B[2], 0.5f), eps);
        float lh = __fadd_rn(__fmul_rn(B[3], 0.5f), eps);
#pragma unroll
        for (int k = 0; k < 4; k++) {
            float rx = __fsub_rn(ax[k], B[0]), ry = __fsub_rn(ay[k], B[1]);
            float xr = __fadd_rn(__fmul_rn(rx, c), __fmul_rn(ry, s));
            float yr = __fadd_rn(__fmul_rn(-rx, s), __fmul_rn(ry, c));
            vl[k] = (fabsf(xr) <= lw) && (fabsf(yr) <= lh);
        }
    }
    {   // vB = in_box(cornB, boxA)
        float c = cosf(A[4]), s = sinf(A[4]);
        float lw = __fadd_rn(__fmul_rn(A[2], 0.5f), eps);
        float lh = __fadd_rn(__fmul_rn(A[3], 0.5f), eps);
#pragma unroll
        for (int k = 0; k < 4; k++) {
            float rx = __fsub_rn(bx[k], A[0]), ry = __fsub_rn(by[k], A[1]);
            float xr = __fadd_rn(__fmul_rn(rx, c), __fmul_rn(ry, s));
            float yr = __fadd_rn(__fmul_rn(-rx, s), __fmul_rn(ry, c));
            vl[4+k] = (fabsf(xr) <= lw) && (fabsf(yr) <= lh);
        }
    }
    float dAx[4],dAy[4],dBx[4],dBy[4];
#pragma unroll
    for (int k = 0; k < 4; k++) {
        dAx[k]=__fsub_rn(ax[(k+1)&3],ax[k]); dAy[k]=__fsub_rn(ay[(k+1)&3],ay[k]);
        dBx[k]=__fsub_rn(bx[(k+1)&3],bx[k]); dBy[k]=__fsub_rn(by[(k+1)&3],by[k]);
    }
#pragma unroll
    for (int i = 0; i < 4; i++) {
#pragma unroll
        for (int j = 0; j < 4; j++) {
            float rx  = __fsub_rn(bx[j], ax[i]), ry = __fsub_rn(by[j], ay[i]);
            float den = __fsub_rn(__fmul_rn(dAx[i], dBy[j]), __fmul_rn(dAy[i], dBx[j]));
            float ad  = fabsf(den);
            float dens = (ad < 1e-9f) ? 1.0f : den;
            float t = __fsub_rn(__fmul_rn(rx, dBy[j]), __fmul_rn(ry, dBx[j])) / dens;
            float u = __fsub_rn(__fmul_rn(rx, dAy[i]), __fmul_rn(ry, dAx[i])) / dens;
            bool v  = (ad > 1e-9f) && (t >= -eps) && (t <= ONEPE) && (u >= -eps) && (u <= ONEPE);
            int o = 8 + i*4 + j;
            px[o] = __fadd_rn(ax[i], __fmul_rn(t, dAx[i]));
            py[o] = __fadd_rn(ay[i], __fmul_rn(t, dAy[i]));
            vl[o] = v;
        }
    }
    int cnt = 0;
#pragma unroll
    for (int k = 0; k < 24; k++) cnt += vl[k] ? 1 : 0;
    float sx = 0.0f, sy = 0.0f;
#pragma unroll
    for (int k = 0; k < 24; k++) {
        float f = vl[k] ? 1.0f : 0.0f;
        sx = __fadd_rn(sx, __fmul_rn(px[k], f));
        sy = __fadd_rn(sy, __fmul_rn(py[k], f));
    }
    int cm = cnt > 1 ? cnt : 1;
    float cenx = sx / (float)cm, ceny = sy / (float)cm;
    int am = 0;
#pragma unroll
    for (int k = 23; k >= 0; k--) if (vl[k]) am = k;
    float anx = px[am], anyy = py[am];
    float qx[24], qy[24], ang[24];
#pragma unroll
    for (int k = 0; k < 24; k++) {
        qx[k] = vl[k] ? px[k] : anx;
        qy[k] = vl[k] ? py[k] : anyy;
        ang[k] = atan2f(__fsub_rn(qy[k], ceny), __fsub_rn(qx[k], cenx));
    }
    int ord[24];
    for (int k = 0; k < 24; k++) ord[k] = k;
    for (int k = 1; k < 24; k++) {
        int o = ord[k]; float a = ang[o]; int m = k - 1;
        while (m >= 0 && ang[ord[m]] > a) { ord[m+1] = ord[m]; m--; }
        ord[m+1] = o;
    }
    float ssum = 0.0f;
    for (int k = 0; k < 24; k++) {
        int k0 = ord[k], k1 = ord[(k + 1) % 24];
        float term = __fsub_rn(__fmul_rn(qx[k0], qy[k1]), __fmul_rn(qx[k1], qy[k0]));
        ssum = __fadd_rn(ssum, term);
    }
    float area = __fmul_rn(0.5f, fabsf(ssum));
    return (cnt >= 3) ? area : 0.0f;
}

// ---------------------------------------------------------------- heavy clips, multi-block, no smem (locals stay in L1)
__global__ void __launch_bounds__(128) k_pairsH() {
    unsigned W = g_sel[4];
    if (W > WCAP) W = WCAP;
    unsigned c0 = blockIdx.x * blockDim.x + threadIdx.x;
    unsigned st = gridDim.x * blockDim.x;
    for (unsigned c = c0; c < W; c += st) {
        unsigned e = g_work[c];
        int i = (int)(e >> 16), j = (int)(e & 0xFFFFu);
        float inter = pair_inter_area(&g_nms[i*5], &g_corn[i*8], &g_nms[j*5], &g_corn[j*8]);
        float S   = __fadd_rn(__fsub_rn(__fadd_rn(g_area[i], g_area[j]), inter), 1e-6f);
        float iou = inter / S;
        if (iou > 0.5f) {
            unsigned pos = atomicAdd(&g_sel[5], 1u);
            if (pos < SPCAP) g_supPairs[pos] = e;
        }
    }
}

// ---------------------------------------------------------------- NMS from suppression pairs + output (1 block, 1024 thr)
__global__ void __launch_bounds__(1024, 1) k_nms_out(float* __restrict__ out) {
    extern __shared__ unsigned s_sup[];          // TOPK*32 words = 125KB
    __shared__ unsigned keepW[32];
    __shared__ unsigned raW[32];
    __shared__ int lst[DETS];
    __shared__ int kcnt;
    int tid = threadIdx.x;
    int nt  = blockDim.x;

    for (int k = tid; k < TOPK*32; k += nt) s_sup[k] = 0u;
    if (tid < 32) { keepW[tid] = 0u; raW[tid] = 0u; }
    __syncthreads();
    for (int i = tid; i < TOPK; i += nt)
        if (g_topVal[i] > neginf()) atomicOr(&keepW[i >> 5], 1u << (i & 31));
    unsigned P = g_sel[5];
    if (P > SPCAP) P = SPCAP;
    for (unsigned p = (unsigned)tid; p < P; p += (unsigned)nt) {
        unsigned e = g_supPairs[p];
        int i = (int)(e >> 16), j = (int)(e & 0xFFFFu);
        atomicOr(&s_sup[i*32 + (j >> 5)], 1u << (j & 31));
        atomicOr(&raW[i >> 5], 1u << (i & 31));
    }
    __syncthreads();

    // serial NMS over rows that suppress something (warp 0)
    if (tid < 32) {
        for (int w = 0; w < 32; w++) {
            unsigned rbits = raW[w];
            while (rbits) {
                int b = __ffs(rbits) - 1;
                rbits &= rbits - 1;
                int i = w * 32 + b;
                if (keepW[w] & (1u << b)) {
                    keepW[tid] &= ~s_sup[i * 32 + tid];
                }
                __syncwarp();
            }
        }
    }
    __syncthreads();

    if (tid == 0) {
        int p = 0;
        for (int w = 0; w < 32 && p < DETS; w++) {
            unsigned m = keepW[w];
            while (m && p < DETS) {
                int b = __ffs(m) - 1;
                m &= m - 1;
                lst[p++] = w * 32 + b;
            }
        }
        kcnt = p;
        g_sel[5] = 0;                                  // self-clean
    }
    __syncthreads();

    for (int r = tid; r < DETS; r += nt) {
        if (r < kcnt) {
            int i = lst[r];
#pragma unroll
            for (int k = 0; k < 5; k++) out[r*5+k] = g_bk[i*5+k];
            out[DETS*5 + r] = (float)g_lab[i];
            out[DETS*6 + r] = g_topVal[i];
        } else {
#pragma unroll
            for (int k = 0; k < 5; k++) out[r*5+k] = 0.0f;
            out[DETS*5 + r] = -1.0f;
            out[DETS*6 + r] = 0.0f;
        }
    }
}

// ---------------------------------------------------------------- launcher
extern "C" void kernel_launch(void* const* d_in, const int* in_sizes, int n_in,
                              void* d_out, int out_size) {
    const float* boxes  = (const float*)d_in[0];
    const float* scores = (const float*)d_in[1];
    const int*   labels = (const int*)d_in[2];
    int n = in_sizes[1];
    int n4 = n / 4;

    static const int NSMEM = TOPK * 32 * (int)sizeof(unsigned);
    cudaFuncSetAttribute(k_nms_out, cudaFuncAttributeMaxDynamicSharedMemorySize, NSMEM);

    k_hist   <<<HIST_GRID, 256>>>((const float4*)scores, n4);
    k_compact<<<CMP_GRID, 256>>>((const float4*)scores, n4);
    k_selprep<<<SEL_GRID, 256>>>(boxes, labels);
    k_pairsH <<<128, 128>>>();
    k_nms_out<<<1, 1024, NSMEM>>>((float*)d_out);
}

// round 9
// speedup vs baseline: 1.6211x; 1.1613x over previous
#include <cuda_runtime.h>
#include <stdint.h>
#include <math.h>

#define TOPK 1000
#define DETS 300
#define NB    4608          // bins over (0.05, 1.0] via fb>>13 - BASE
#define CH    18            // NB / 256
#define BASE  125542        // 0x3D4CCCCD >> 13  (0.05f)
#define CAND_CAP 32768
#define SELCAP   6144
#define NCLS  80
#define WCAP  8192
#define SPCAP 8192
#define SP_SH 2048
#define FAST_T 0.999f

#define HIST_GRID 148
#define CMP_GRID  592
#define SEL_GRID  128
#define PAIR_GRID 32

__device__ unsigned int       g_hist1[NB];
__device__ unsigned int       g_sel[8];     // [0]=B1 [1]=pairs ticket [2]=cand cnt [3]=skip flag [4]=work cnt [5]=sup-pair cnt [6]=hist ticket [7]=sel ticket
__device__ unsigned long long g_cand[CAND_CAP];
__device__ unsigned int       g_work[WCAP];
__device__ unsigned int       g_supPairs[SPCAP];
__device__ int                g_topIdx[TOPK];
__device__ float              g_topVal[TOPK];
__device__ float              g_bk[TOPK*5];      // original boxes (output)
__device__ float              g_nms[TOPK*5];     // offset boxes (NMS domain)
__device__ float              g_corn[TOPK*8];
__device__ float              g_aabb[TOPK*4];    // minx,maxx,miny,maxy
__device__ float              g_area[TOPK];
__device__ int                g_lab[TOPK];

__device__ __forceinline__ float neginf() { return __int_as_float(0xff800000); }

__device__ __forceinline__ int bin_of(unsigned fb) {
    int b = (int)(fb >> 13) - BASE;
    if (b < 0) b = 0;
    if (b > NB - 1) b = NB - 1;
    return b;
}

__device__ __forceinline__ float sel4(int i, float a, float b, float c, float d) {
    return (i == 0) ? a : (i == 1) ? b : (i == 2) ? c : d;
}

// ---------------------------------------------------------------- pass 1: histogram + opportunistic compact + fused findb1
__global__ void k_hist(const float4* __restrict__ sc4, int n4) {
    __shared__ unsigned int h[NB];
    __shared__ unsigned csum[256];
    __shared__ int isLast;
    int tid = threadIdx.x;
    for (int k = tid; k < NB; k += blockDim.x) h[k] = 0;
    __syncthreads();
    int i0 = blockIdx.x * blockDim.x + tid;
    int S  = gridDim.x * blockDim.x;
    for (int p = i0; p < n4; p += 4 * S) {
        int p1 = p + S, p2 = p + 2*S, p3 = p + 3*S;
        float4 v0 = sc4[p];
        float4 v1 = (p1 < n4) ? sc4[p1] : make_float4(0,0,0,0);
        float4 v2 = (p2 < n4) ? sc4[p2] : make_float4(0,0,0,0);
        float4 v3 = (p3 < n4) ? sc4[p3] : make_float4(0,0,0,0);
        float vs[16] = { v0.x,v0.y,v0.z,v0.w, v1.x,v1.y,v1.z,v1.w,
                         v2.x,v2.y,v2.z,v2.w, v3.x,v3.y,v3.z,v3.w };
        int  pq[4] = { p, p1, p2, p3 };
#pragma unroll
        for (int l = 0; l < 16; l++) {
            float s = vs[l];
            if (s > 0.05f) {
                unsigned fb = __float_as_uint(s);
                atomicAdd(&h[bin_of(fb)], 1u);
                if (s > FAST_T) {   // opportunistic compact
                    unsigned pos = atomicAdd(&g_sel[2], 1u);
                    if (pos < CAND_CAP) {
                        unsigned idx = (unsigned)(pq[l >> 2] * 4 + (l & 3));
                        g_cand[pos] = ((unsigned long long)fb << 32) |
                                      (unsigned long long)(0xFFFFFFFFu - idx);
                    }
                }
            }
        }
    }
    __syncthreads();
    for (int k = tid; k < NB; k += blockDim.x) {
        unsigned v = h[k];
        if (v) atomicAdd(&g_hist1[k], v);
    }
    __threadfence();
    if (tid == 0) {
        unsigned t = atomicAdd(&g_sel[6], 1u);
        isLast = (t == gridDim.x - 1);
    }
    __syncthreads();
    if (!isLast) return;
    __threadfence();
    // ---- fused findb1 + self-clean ----
    for (int k = tid; k < NB; k += blockDim.x) { h[k] = g_hist1[k]; g_hist1[k] = 0; }
    __syncthreads();
    unsigned s = 0;
    for (int b = tid * CH; b < tid * CH + CH; b++) s += h[b];
    csum[tid] = s;
    __syncthreads();
    if (tid == 0) {
        unsigned cum = 0; int B1 = -1;
        for (int c = 255; c >= 0; c--) {
            if (cum + csum[c] >= TOPK) {
                for (int b = c * CH + CH - 1; b >= c * CH; b--) {
                    if (cum + h[b] >= TOPK) { B1 = b; break; }
                    cum += h[b];
                }
                break;
            }
            cum += csum[c];
        }
        if (B1 < 0) B1 = 0;
        g_sel[0] = (unsigned)B1;
        g_sel[6] = 0;                                  // reset ticket
        unsigned ct = g_sel[2];
        int skip = (ct >= TOPK && ct <= CAND_CAP) ? 1 : 0;
        g_sel[3] = (unsigned)skip;
        if (!skip) g_sel[2] = 0;                       // compact pass rebuilds
    }
}

// ---------------------------------------------------------------- pass 2 (fallback only): compact (bin >= B1)
__global__ void k_compact(const float4* __restrict__ sc4, int n4) {
    if (g_sel[3]) return;                              // fast path: already have candidates
    unsigned B1 = g_sel[0];
    int i0 = blockIdx.x * blockDim.x + threadIdx.x;
    int S  = gridDim.x * blockDim.x;
    for (int p = i0; p < n4; p += 2 * S) {
        int p1 = p + S;
        float4 v0 = sc4[p];
        float4 v1 = (p1 < n4) ? sc4[p1] : make_float4(0,0,0,0);
        float vs[8] = { v0.x,v0.y,v0.z,v0.w, v1.x,v1.y,v1.z,v1.w };
        int   pb[2] = { p, p1 };
#pragma unroll
        for (int l = 0; l < 8; l++) {
            float s = vs[l];
            if (s > 0.05f) {
                unsigned fb = __float_as_uint(s);
                if (bin_of(fb) >= (int)B1) {
                    unsigned pos = atomicAdd(&g_sel[2], 1u);
                    if (pos < CAND_CAP) {
                        unsigned idx = (unsigned)(pb[l >> 2] * 4 + (l & 3));
                        g_cand[pos] = ((unsigned long long)fb << 32) |
                                      (unsigned long long)(0xFFFFFFFFu - idx);
                    }
                }
            }
        }
    }
}

// ---------------------------------------------------------------- select (16-lane rank) + fused prep + AABB sieve (last block)
__global__ void k_selprep(const float* __restrict__ boxes, const int* __restrict__ labels) {
    __shared__ unsigned long long sk[SELCAP];
    __shared__ int isLast;
    __shared__ int s_cc[NCLS];
    __shared__ int s_off[NCLS + 1];
    __shared__ int s_fill[NCLS];
    unsigned C = g_sel[2];
    if (C > CAND_CAP) C = CAND_CAP;
    int tid = threadIdx.x;
    bool small = (C <= SELCAP);
    const unsigned long long* base;
    if (small) {
        for (unsigned k = (unsigned)tid; k < C; k += blockDim.x) sk[k] = g_cand[k];
        base = sk;
    } else {
        base = g_cand;
    }
    __syncthreads();

    unsigned lane  = (unsigned)tid & 15u;
    unsigned gidx  = (unsigned)(blockIdx.x * blockDim.x + tid) >> 4;
    unsigned cstr  = (unsigned)(gridDim.x * blockDim.x) >> 4;
    unsigned nIter = (C + cstr - 1) / cstr;
    for (unsigned it = 0; it < nIter; it++) {
        unsigned c = gidx + it * cstr;
        bool act = (c < C);
        unsigned long long key = act ? base[c] : 0ULL;
        unsigned rank = 0;
        unsigned k = lane;
        for (; k + 48 < C; k += 64) {
            unsigned long long a0 = base[k], a1 = base[k+16], a2 = base[k+32], a3 = base[k+48];
            rank += (a0 > key) + (a1 > key) + (a2 > key) + (a3 > key);
        }
        for (; k < C; k += 16) rank += (base[k] > key) ? 1u : 0u;
        rank += __shfl_down_sync(0xffffffffu, rank, 8, 16);
        rank += __shfl_down_sync(0xffffffffu, rank, 4, 16);
        rank += __shfl_down_sync(0xffffffffu, rank, 2, 16);
        rank += __shfl_down_sync(0xffffffffu, rank, 1, 16);
        if (act && lane == 0 && rank < TOPK) {
            g_topIdx[rank] = (int)(0xFFFFFFFFu - (unsigned)(key & 0xFFFFFFFFull));
            g_topVal[rank] = __uint_as_float((unsigned)(key >> 32));
        }
    }
    __threadfence();
    __syncthreads();
    if (tid == 0) {
        unsigned t = atomicAdd(&g_sel[7], 1u);
        isLast = (t == gridDim.x - 1);
    }
    __syncthreads();
    if (!isLast) return;
    __threadfence();

    // ---- fused prep: gather + offset + corners + AABB ----
    if (tid < NCLS) { s_cc[tid] = 0; s_fill[tid] = 0; }
    if (tid == 0) { g_sel[4] = 0; g_sel[5] = 0; g_sel[7] = 0; g_sel[2] = 0; g_sel[3] = 0; }
    __syncthreads();
    for (int i = tid; i < TOPK; i += blockDim.x) {
        int idx = g_topIdx[i];
        if (idx < 0) { g_lab[i] = -1 - NCLS; g_area[i] = 0.0f; continue; }
        float cx = boxes[idx*5+0], cy = boxes[idx*5+1];
        float w  = boxes[idx*5+2], h  = boxes[idx*5+3];
        float a  = boxes[idx*5+4];
        g_bk[i*5+0]=cx; g_bk[i*5+1]=cy; g_bk[i*5+2]=w; g_bk[i*5+3]=h; g_bk[i*5+4]=a;
        int lab = labels[idx];
        g_lab[i] = lab;
        float off = __fmul_rn((float)lab, 10000.0f);
        float cxo = __fadd_rn(cx, off);
        float cyo = __fadd_rn(cy, off);
        g_nms[i*5+0]=cxo; g_nms[i*5+1]=cyo; g_nms[i*5+2]=w; g_nms[i*5+3]=h; g_nms[i*5+4]=a;
        g_area[i] = __fmul_rn(w, h);

        float c = cosf(a), s = sinf(a);
        float dx = __fmul_rn(w, 0.5f), dy = __fmul_rn(h, 0.5f);
        float ox[4] = { dx, -dx, -dx,  dx };
        float oy[4] = { dy,  dy, -dy, -dy };
        float mnx =  3.4e38f, mxx = -3.4e38f, mny = 3.4e38f, mxy = -3.4e38f;
#pragma unroll
        for (int j = 0; j < 4; j++) {
            float x = __fsub_rn(__fadd_rn(cxo, __fmul_rn(ox[j], c)), __fmul_rn(oy[j], s));
            float y = __fadd_rn(__fadd_rn(cyo, __fmul_rn(ox[j], s)), __fmul_rn(oy[j], c));
            g_corn[i*8 + 2*j]     = x;
            g_corn[i*8 + 2*j + 1] = y;
            mnx = fminf(mnx, x); mxx = fmaxf(mxx, x);
            mny = fminf(mny, y); mxy = fmaxf(mxy, y);
        }
        g_aabb[i*4+0]=mnx; g_aabb[i*4+1]=mxx; g_aabb[i*4+2]=mny; g_aabb[i*4+3]=mxy;
        if (lab >= 0 && lab < NCLS) atomicAdd(&s_cc[lab], 1);
    }
    __syncthreads();

    // ---- class CSR + stage AABBs into sk space ----
    float* s_aabb = (float*)sk;                 // 4000 floats (16KB)  — sk dead now
    int*   s_cls  = (int*)(s_aabb + TOPK*4);    // 1000 ints
    if (tid == 0) {
        int acc = 0;
        for (int c = 0; c < NCLS; c++) { s_off[c] = acc; acc += s_cc[c]; }
        s_off[NCLS] = acc;
    }
    __syncthreads();
    for (int i = tid; i < TOPK; i += blockDim.x) {
        ((float4*)s_aabb)[i] = ((const float4*)g_aabb)[i];
        int lab = g_lab[i];
        if (lab >= 0 && lab < NCLS) {
            int pos = atomicAdd(&s_fill[lab], 1);
            s_cls[s_off[lab] + pos] = i;
        }
    }
    __syncthreads();

    // ---- AABB sieve -> global worklist ----
    for (int c = 0; c < NCLS; c++) {
        int n = s_cc[c];
        if (n < 2) continue;
        const int* cl = &s_cls[s_off[c]];
        for (int t = tid; t < n*n; t += blockDim.x) {
            int i_ = t / n, j_ = t - i_ * n;
            if (i_ >= j_) continue;
            int a = cl[i_], b = cl[j_];
            if (a > b) { int tmp = a; a = b; b = tmp; }
            const float M = 1.0f;
            if (s_aabb[a*4+0] > s_aabb[b*4+1] + M || s_aabb[b*4+0] > s_aabb[a*4+1] + M ||
                s_aabb[a*4+2] > s_aabb[b*4+3] + M || s_aabb[b*4+2] > s_aabb[a*4+3] + M) continue;
            unsigned pos = atomicAdd(&g_sel[4], 1u);
            if (pos < WCAP) g_work[pos] = ((unsigned)a << 16) | (unsigned)b;
        }
    }
}

// ---------------------------------------------------------------- warp-cooperative exact clip (register-resident)
// One pair per warp; lane k (<24) owns candidate point k. All order-sensitive
// fp32 reductions performed as the exact sequential __fadd_rn chain over k=0..23,
// matching the scalar replica of the reference bit-for-bit.
__device__ __forceinline__ float warp_inter_area(int bi, int bj, int lane) {
    const unsigned FULL = 0xffffffffu;
    const float eps = 1e-6f;
    const float ONEPE = 1.000001f;
    const float* A  = &g_nms[bi*5];
    const float* B  = &g_nms[bj*5];
    const float* cA = &g_corn[bi*8];
    const float* cB = &g_corn[bj*8];
    float ax0=cA[0], ay0=cA[1], ax1=cA[2], ay1=cA[3], ax2=cA[4], ay2=cA[5], ax3=cA[6], ay3=cA[7];
    float bx0=cB[0], by0=cB[1], bx1=cB[2], by1=cB[3], bx2=cB[4], by2=cB[5], bx3=cB[6], by3=cB[7];
    float Acx=A[0], Acy=A[1], Aw=A[2], Ah=A[3], Aa=A[4];
    float Bcx=B[0], Bcy=B[1], Bw=B[2], Bh=B[3], Ba=B[4];

    // edge vectors (all lanes)
    float dAx0=__fsub_rn(ax1,ax0), dAy0=__fsub_rn(ay1,ay0);
    float dAx1=__fsub_rn(ax2,ax1), dAy1=__fsub_rn(ay2,ay1);
    float dAx2=__fsub_rn(ax3,ax2), dAy2=__fsub_rn(ay3,ay2);
    float dAx3=__fsub_rn(ax0,ax3), dAy3=__fsub_rn(ay0,ay3);
    float dBx0=__fsub_rn(bx1,bx0), dBy0=__fsub_rn(by1,by0);
    float dBx1=__fsub_rn(bx2,bx1), dBy1=__fsub_rn(by2,by1);
    float dBx2=__fsub_rn(bx3,bx2), dBy2=__fsub_rn(by3,by2);
    float dBx3=__fsub_rn(bx0,bx3), dBy3=__fsub_rn(by0,by3);

    float px = 0.0f, py = 0.0f;
    bool  vl = false;
    if (lane < 8) {
        int  c4  = lane & 3;
        bool isA = lane < 4;
        float ptx = isA ? sel4(c4, ax0,ax1,ax2,ax3) : sel4(c4, bx0,bx1,bx2,bx3);
        float pty = isA ? sel4(c4, ay0,ay1,ay2,ay3) : sel4(c4, by0,by1,by2,by3);
        float tcx = isA ? Bcx : Acx;
        float tcy = isA ? Bcy : Acy;
        float tw  = isA ? Bw  : Aw;
        float th  = isA ? Bh  : Ah;
        float ta  = isA ? Ba  : Aa;
        float cc = cosf(ta), ss = sinf(ta);
        float rx = __fsub_rn(ptx, tcx), ry = __fsub_rn(pty, tcy);
        float xr = __fadd_rn(__fmul_rn(rx, cc), __fmul_rn(ry, ss));
        float yr = __fadd_rn(__fmul_rn(-rx, ss), __fmul_rn(ry, cc));
        float lw = __fadd_rn(__fmul_rn(tw, 0.5f), eps);
        float lh = __fadd_rn(__fmul_rn(th, 0.5f), eps);
        vl = (fabsf(xr) <= lw) && (fabsf(yr) <= lh);
        px = ptx; py = pty;
    } else if (lane < 24) {
        int ii = (lane - 8) >> 2, jj = (lane - 8) & 3;
        float axi = sel4(ii, ax0,ax1,ax2,ax3), ayi = sel4(ii, ay0,ay1,ay2,ay3);
        float dxi = sel4(ii, dAx0,dAx1,dAx2,dAx3), dyi = sel4(ii, dAy0,dAy1,dAy2,dAy3);
        float bxj = sel4(jj, bx0,bx1,bx2,bx3), byj = sel4(jj, by0,by1,by2,by3);
        float exj = sel4(jj, dBx0,dBx1,dBx2,dBx3), eyj = sel4(jj, dBy0,dBy1,dBy2,dBy3);
        float rx  = __fsub_rn(bxj, axi), ry = __fsub_rn(byj, ayi);
        float den = __fsub_rn(__fmul_rn(dxi, eyj), __fmul_rn(dyi, exj));
        float ad  = fabsf(den);
        float dens = (ad < 1e-9f) ? 1.0f : den;
        float t = __fsub_rn(__fmul_rn(rx, eyj), __fmul_rn(ry, exj)) / dens;
        float u = __fsub_rn(__fmul_rn(rx, dyi), __fmul_rn(ry, dxi)) / dens;
        vl = (ad > 1e-9f) && (t >= -eps) && (t <= ONEPE) && (u >= -eps) && (u <= ONEPE);
        px = __fadd_rn(axi, __fmul_rn(t, dxi));
        py = __fadd_rn(ayi, __fmul_rn(t, dyi));
    }

    unsigned bal = __ballot_sync(FULL, vl) & 0x00FFFFFFu;
    int cnt = __popc(bal);

    // centroid: sequential sum k=0..23 (exact reference order)
    float f = vl ? 1.0f : 0.0f;
    float contx = __fmul_rn(px, f);
    float conty = __fmul_rn(py, f);
    float sx = 0.0f, sy = 0.0f;
#pragma unroll
    for (int m = 0; m < 24; m++) {
        float vx = __shfl_sync(FULL, contx, m);
        float vy = __shfl_sync(FULL, conty, m);
        sx = __fadd_rn(sx, vx);
        sy = __fadd_rn(sy, vy);
    }
    int cm = cnt > 1 ? cnt : 1;
    float cenx = sx / (float)cm, ceny = sy / (float)cm;

    // anchor = first valid point (else point 0)
    int am = bal ? (__ffs(bal) - 1) : 0;
    float anx  = __shfl_sync(FULL, px, am);
    float anyy = __shfl_sync(FULL, py, am);

    float qx = vl ? px : anx;
    float qy = vl ? py : anyy;
    float ang = atan2f(__fsub_rn(qy, ceny), __fsub_rn(qx, cenx));

    // stable rank == stable argsort ascending
    int rank = (lane < 24) ? 0 : (100 + lane);
#pragma unroll
    for (int m = 0; m < 24; m++) {
        float am_ = __shfl_sync(FULL, ang, m);
        if (lane < 24 && m != lane) {
            bool less = (am_ < ang) || (am_ == ang && m < lane);
            rank += less ? 1 : 0;
        }
    }

    // inverse permutation: lane p gets the point with rank p
    float X = 0.0f, Y = 0.0f;
#pragma unroll
    for (int m = 0; m < 24; m++) {
        int   rm = __shfl_sync(FULL, rank, m);
        float xm = __shfl_sync(FULL, qx, m);
        float ym = __shfl_sync(FULL, qy, m);
        if (rm == lane) { X = xm; Y = ym; }
    }
    int nxt = (lane == 23) ? 0 : lane + 1;
    float Xn = __shfl_sync(FULL, X, nxt);
    float Yn = __shfl_sync(FULL, Y, nxt);
    float term = __fsub_rn(__fmul_rn(X, Yn), __fmul_rn(Xn, Y));

    // shoelace: sequential sum over sorted positions 0..23 (exact order)
    float ssum = 0.0f;
#pragma unroll
    for (int m = 0; m < 24; m++) {
        float tv = __shfl_sync(FULL, term, m);
        ssum = __fadd_rn(ssum, tv);
    }
    float area = __fmul_rn(0.5f, fabsf(ssum));
    return (cnt >= 3) ? area : 0.0f;
}

// ---------------------------------------------------------------- heavy clips (warp-coop) + fused NMS + output (last block)
__global__ void __launch_bounds__(256) k_pairsH(float* __restrict__ out) {
    int tid  = threadIdx.x;
    int lane = tid & 31;
    unsigned W = g_sel[4];
    if (W > WCAP) W = WCAP;
    unsigned gw = (unsigned)(blockIdx.x * blockDim.x + tid) >> 5;
    unsigned nw = (unsigned)(gridDim.x * blockDim.x) >> 5;
    for (unsigned c = gw; c < W; c += nw) {
        unsigned e = g_work[c];
        int i = (int)(e >> 16), j = (int)(e & 0xFFFFu);
        float inter = warp_inter_area(i, j, lane);
        if (lane == 0) {
            float S   = __fadd_rn(__fsub_rn(__fadd_rn(g_area[i], g_area[j]), inter), 1e-6f);
            float iou = inter / S;
            if (iou > 0.5f) {
                unsigned pos = atomicAdd(&g_sel[5], 1u);
                if (pos < SPCAP) g_supPairs[pos] = e;
            }
        }
    }

    // ---- last block: serial NMS over suppression pairs + output ----
    __shared__ int isLast;
    __threadfence();
    __syncthreads();
    if (tid == 0) {
        unsigned t = atomicAdd(&g_sel[1], 1u);
        isLast = (t == gridDim.x - 1);
    }
    __syncthreads();
    if (!isLast) return;
    __threadfence();

    __shared__ unsigned keepW[32];
    __shared__ unsigned raW[32];
    __shared__ unsigned sp[SP_SH];
    __shared__ int lst[DETS];
    __shared__ int kcnt;
    if (tid < 32) { keepW[tid] = 0u; raW[tid] = 0u; }
    __syncthreads();
    for (int i = tid; i < TOPK; i += blockDim.x)
        if (g_topVal[i] > neginf()) atomicOr(&keepW[i >> 5], 1u << (i & 31));
    unsigned P = g_sel[5];
    if (P > SPCAP) P = SPCAP;
    unsigned Ps = (P > SP_SH) ? SP_SH : P;
    for (unsigned p = (unsigned)tid; p < P; p += (unsigned)blockDim.x) {
        unsigned e = g_supPairs[p];
        if (p < Ps) sp[p] = e;
        unsigned i = e >> 16;
        atomicOr(&raW[i >> 5], 1u << (i & 31));
    }
    __syncthreads();

    if (tid == 0) {
        for (int w = 0; w < 32; w++) {
            unsigned rb = raW[w];
            while (rb) {
                int b = __ffs(rb) - 1;
                rb &= rb - 1;
                int i = w * 32 + b;
                if (keepW[w] & (1u << b)) {
                    for (unsigned p = 0; p < Ps; p++) {
                        unsigned e = sp[p];
                        if ((int)(e >> 16) == i) {
                            int j = (int)(e & 0xFFFFu);
                            keepW[j >> 5] &= ~(1u << (j & 31));
                        }
                    }
                    for (unsigned p = Ps; p < P; p++) {
                        unsigned e = g_supPairs[p];
                        if ((int)(e >> 16) == i) {
                            int j = (int)(e & 0xFFFFu);
                            keepW[j >> 5] &= ~(1u << (j & 31));
                        }
                    }
                }
            }
        }
        int p = 0;
        for (int w = 0; w < 32 && p < DETS; w++) {
            unsigned m = keepW[w];
            while (m && p < DETS) {
                int b = __ffs(m) - 1;
                m &= m - 1;
                lst[p++] = w * 32 + b;
            }
        }
        kcnt = p;
        g_sel[1] = 0;                                  // self-clean ticket
    }
    __syncthreads();

    for (int r = tid; r < DETS; r += blockDim.x) {
        if (r < kcnt) {
            int i = lst[r];
#pragma unroll
            for (int k = 0; k < 5; k++) out[r*5+k] = g_bk[i*5+k];
            out[DETS*5 + r] = (float)g_lab[i];
            out[DETS*6 + r] = g_topVal[i];
        } else {
#pragma unroll
            for (int k = 0; k < 5; k++) out[r*5+k] = 0.0f;
            out[DETS*5 + r] = -1.0f;
            out[DETS*6 + r] = 0.0f;
        }
    }
}

// ---------------------------------------------------------------- launcher
extern "C" void kernel_launch(void* const* d_in, const int* in_sizes, int n_in,
                              void* d_out, int out_size) {
    const float* boxes  = (const float*)d_in[0];
    const float* scores = (const float*)d_in[1];
    const int*   labels = (const int*)d_in[2];
    int n = in_sizes[1];
    int n4 = n / 4;

    k_hist   <<<HIST_GRID, 256>>>((const float4*)scores, n4);
    k_compact<<<CMP_GRID, 256>>>((const float4*)scores, n4);
    k_selprep<<<SEL_GRID, 256>>>(boxes, labels);
    k_pairsH <<<PAIR_GRID, 256>>>((float*)d_out);
}

// round 10
// speedup vs baseline: 1.8496x; 1.1409x over previous
#include <cuda_runtime.h>
#include <stdint.h>
#include <math.h>

#define TOPK 1000
#define DETS 300
#define NB    4608          // fallback bins via fb>>13 - BASE
#define CH    18            // NB / 256
#define BASE  125542        // 0x3D4CCCCD >> 13  (0.05f)
#define CAND_CAP 32768
#define SELCAP   6144
#define NCLS  80
#define WCAP  8192
#define SPCAP 8192
#define MAXSLOTS 256
#define FAST_T 0.999f

#define FAST_GRID 592
#define HIST_GRID 148
#define SEL_GRID  128
#define PAIR_GRID 32

__device__ unsigned int       g_hist1[NB];
__device__ unsigned int       g_sel[8];     // [0]=B1 [1]=pairs ticket [2]=cand cnt [3]=skip flag [4]=work cnt [5]=sup cnt [6]=ticket A [7]=sel ticket
__device__ unsigned long long g_cand[CAND_CAP];
__device__ unsigned int       g_work[WCAP];
__device__ unsigned int       g_supPairs[SPCAP];
__device__ int                g_topIdx[TOPK];
__device__ float              g_topVal[TOPK];
__device__ float              g_bk[TOPK*5];      // original boxes (output)
__device__ float              g_nms[TOPK*5];     // offset boxes (NMS domain)
__device__ float              g_corn[TOPK*8];
__device__ float              g_aabb[TOPK*4];
__device__ float              g_area[TOPK];
__device__ int                g_lab[TOPK];

__device__ __forceinline__ float neginf() { return __int_as_float(0xff800000); }

__device__ __forceinline__ int bin_of(unsigned fb) {
    int b = (int)(fb >> 13) - BASE;
    if (b < 0) b = 0;
    if (b > NB - 1) b = NB - 1;
    return b;
}

__device__ __forceinline__ float sel4(int i, float a, float b, float c, float d) {
    return (i == 0) ? a : (i == 1) ? b : (i == 2) ? c : d;
}

// ---------------------------------------------------------------- pass 1: fast compact (s > FAST_T), atomic-free streaming
__global__ void k_fast(const float4* __restrict__ sc4, int n4) {
    __shared__ int isLast;
    int tid = threadIdx.x;
    int i0 = blockIdx.x * blockDim.x + tid;
    int S  = gridDim.x * blockDim.x;
    for (int p = i0; p < n4; p += 4 * S) {
        int p1 = p + S, p2 = p + 2*S, p3 = p + 3*S;
        float4 v0 = sc4[p];
        float4 v1 = (p1 < n4) ? sc4[p1] : make_float4(0,0,0,0);
        float4 v2 = (p2 < n4) ? sc4[p2] : make_float4(0,0,0,0);
        float4 v3 = (p3 < n4) ? sc4[p3] : make_float4(0,0,0,0);
        float vs[16] = { v0.x,v0.y,v0.z,v0.w, v1.x,v1.y,v1.z,v1.w,
                         v2.x,v2.y,v2.z,v2.w, v3.x,v3.y,v3.z,v3.w };
        int  pq[4] = { p, p1, p2, p3 };
#pragma unroll
        for (int l = 0; l < 16; l++) {
            float s = vs[l];
            if (s > FAST_T) {
                unsigned pos = atomicAdd(&g_sel[2], 1u);
                if (pos < CAND_CAP) {
                    unsigned idx = (unsigned)(pq[l >> 2] * 4 + (l & 3));
                    g_cand[pos] = ((unsigned long long)__float_as_uint(s) << 32) |
                                  (unsigned long long)(0xFFFFFFFFu - idx);
                }
            }
        }
    }
    __threadfence();
    __syncthreads();
    if (tid == 0) {
        unsigned t = atomicAdd(&g_sel[6], 1u);
        isLast = (t == gridDim.x - 1);
    }
    __syncthreads();
    if (!isLast) return;
    if (tid == 0) {
        unsigned ct = g_sel[2];
        int skip = (ct >= TOPK && ct <= CAND_CAP) ? 1 : 0;
        g_sel[3] = (unsigned)skip;
        if (!skip) g_sel[2] = 0;     // fallback rebuilds
        g_sel[6] = 0;
    }
}

// ---------------------------------------------------------------- fallback only: histogram + findb1 + compact (early-exit in fast path)
__global__ void k_histcmp(const float4* __restrict__ sc4, int n4) {
    if (g_sel[3]) return;            // fast path succeeded
    __shared__ unsigned int h[NB];
    __shared__ unsigned csum[256];
    __shared__ int isLast;
    int tid = threadIdx.x;
    for (int k = tid; k < NB; k += blockDim.x) h[k] = 0;
    __syncthreads();
    int i0 = blockIdx.x * blockDim.x + tid;
    int S  = gridDim.x * blockDim.x;
    for (int p = i0; p < n4; p += S) {
        float4 v = sc4[p];
        float vs[4] = { v.x, v.y, v.z, v.w };
#pragma unroll
        for (int l = 0; l < 4; l++)
            if (vs[l] > 0.05f) atomicAdd(&h[bin_of(__float_as_uint(vs[l]))], 1u);
    }
    __syncthreads();
    for (int k = tid; k < NB; k += blockDim.x) {
        unsigned v = h[k];
        if (v) atomicAdd(&g_hist1[k], v);
    }
    __threadfence();
    if (tid == 0) {
        unsigned t = atomicAdd(&g_sel[6], 1u);
        isLast = (t == gridDim.x - 1);
    }
    __syncthreads();
    if (!isLast) return;
    __threadfence();
    for (int k = tid; k < NB; k += blockDim.x) { h[k] = g_hist1[k]; g_hist1[k] = 0; }
    __syncthreads();
    unsigned s = 0;
    for (int b = tid * CH; b < tid * CH + CH; b++) s += h[b];
    csum[tid] = s;
    __syncthreads();
    __shared__ int sB1;
    if (tid == 0) {
        unsigned cum = 0; int B1 = -1;
        for (int c = 255; c >= 0; c--) {
            if (cum + csum[c] >= TOPK) {
                for (int b = c * CH + CH - 1; b >= c * CH; b--) {
                    if (cum + h[b] >= TOPK) { B1 = b; break; }
                    cum += h[b];
                }
                break;
            }
            cum += csum[c];
        }
        if (B1 < 0) B1 = 0;
        sB1 = B1;
        g_sel[6] = 0;
    }
    __syncthreads();
    // compact within this (last) block — fallback only, perf irrelevant
    int B1 = sB1;
    for (int p = tid; p < n4; p += blockDim.x) {
        float4 v = sc4[p];
        float vs[4] = { v.x, v.y, v.z, v.w };
#pragma unroll
        for (int l = 0; l < 4; l++) {
            float sv = vs[l];
            if (sv > 0.05f) {
                unsigned fb = __float_as_uint(sv);
                if (bin_of(fb) >= B1) {
                    unsigned pos = atomicAdd(&g_sel[2], 1u);
                    if (pos < CAND_CAP) {
                        unsigned idx = (unsigned)(p * 4 + l);
                        g_cand[pos] = ((unsigned long long)fb << 32) |
                                      (unsigned long long)(0xFFFFFFFFu - idx);
                    }
                }
            }
        }
    }
}

// ---------------------------------------------------------------- select (16-lane rank) + fused prep + AABB sieve (last block)
__global__ void k_selprep(const float* __restrict__ boxes, const int* __restrict__ labels) {
    __shared__ unsigned long long sk[SELCAP];
    __shared__ int isLast;
    __shared__ int s_cc[NCLS];
    __shared__ int s_off[NCLS + 1];
    __shared__ int s_fill[NCLS];
    unsigned C = g_sel[2];
    if (C > CAND_CAP) C = CAND_CAP;
    int tid = threadIdx.x;
    bool small = (C <= SELCAP);
    const unsigned long long* base;
    if (small) {
        for (unsigned k = (unsigned)tid; k < C; k += blockDim.x) sk[k] = g_cand[k];
        base = sk;
    } else {
        base = g_cand;
    }
    __syncthreads();

    unsigned lane  = (unsigned)tid & 15u;
    unsigned gidx  = (unsigned)(blockIdx.x * blockDim.x + tid) >> 4;
    unsigned cstr  = (unsigned)(gridDim.x * blockDim.x) >> 4;
    unsigned nIter = (C + cstr - 1) / cstr;
    for (unsigned it = 0; it < nIter; it++) {
        unsigned c = gidx + it * cstr;
        bool act = (c < C);
        unsigned long long key = act ? base[c] : 0ULL;
        unsigned rank = 0;
        unsigned k = lane;
        for (; k + 48 < C; k += 64) {
            unsigned long long a0 = base[k], a1 = base[k+16], a2 = base[k+32], a3 = base[k+48];
            rank += (a0 > key) + (a1 > key) + (a2 > key) + (a3 > key);
        }
        for (; k < C; k += 16) rank += (base[k] > key) ? 1u : 0u;
        rank += __shfl_down_sync(0xffffffffu, rank, 8, 16);
        rank += __shfl_down_sync(0xffffffffu, rank, 4, 16);
        rank += __shfl_down_sync(0xffffffffu, rank, 2, 16);
        rank += __shfl_down_sync(0xffffffffu, rank, 1, 16);
        if (act && lane == 0 && rank < TOPK) {
            g_topIdx[rank] = (int)(0xFFFFFFFFu - (unsigned)(key & 0xFFFFFFFFull));
            g_topVal[rank] = __uint_as_float((unsigned)(key >> 32));
        }
    }
    __threadfence();
    __syncthreads();
    if (tid == 0) {
        unsigned t = atomicAdd(&g_sel[7], 1u);
        isLast = (t == gridDim.x - 1);
    }
    __syncthreads();
    if (!isLast) return;
    __threadfence();

    // ---- fused prep: gather + offset + corners + AABB ----
    if (tid < NCLS) { s_cc[tid] = 0; s_fill[tid] = 0; }
    if (tid == 0) { g_sel[4] = 0; g_sel[5] = 0; g_sel[7] = 0; g_sel[2] = 0; g_sel[3] = 0; }
    __syncthreads();
    for (int i = tid; i < TOPK; i += blockDim.x) {
        int idx = g_topIdx[i];
        if (idx < 0) { g_lab[i] = -1 - NCLS; g_area[i] = 0.0f; continue; }
        float cx = boxes[idx*5+0], cy = boxes[idx*5+1];
        float w  = boxes[idx*5+2], h  = boxes[idx*5+3];
        float a  = boxes[idx*5+4];
        g_bk[i*5+0]=cx; g_bk[i*5+1]=cy; g_bk[i*5+2]=w; g_bk[i*5+3]=h; g_bk[i*5+4]=a;
        int lab = labels[idx];
        g_lab[i] = lab;
        float off = __fmul_rn((float)lab, 10000.0f);
        float cxo = __fadd_rn(cx, off);
        float cyo = __fadd_rn(cy, off);
        g_nms[i*5+0]=cxo; g_nms[i*5+1]=cyo; g_nms[i*5+2]=w; g_nms[i*5+3]=h; g_nms[i*5+4]=a;
        g_area[i] = __fmul_rn(w, h);

        float c = cosf(a), s = sinf(a);
        float dx = __fmul_rn(w, 0.5f), dy = __fmul_rn(h, 0.5f);
        float ox[4] = { dx, -dx, -dx,  dx };
        float oy[4] = { dy,  dy, -dy, -dy };
        float mnx =  3.4e38f, mxx = -3.4e38f, mny = 3.4e38f, mxy = -3.4e38f;
#pragma unroll
        for (int j = 0; j < 4; j++) {
            float x = __fsub_rn(__fadd_rn(cxo, __fmul_rn(ox[j], c)), __fmul_rn(oy[j], s));
            float y = __fadd_rn(__fadd_rn(cyo, __fmul_rn(ox[j], s)), __fmul_rn(oy[j], c));
            g_corn[i*8 + 2*j]     = x;
            g_corn[i*8 + 2*j + 1] = y;
            mnx = fminf(mnx, x); mxx = fmaxf(mxx, x);
            mny = fminf(mny, y); mxy = fmaxf(mxy, y);
        }
        g_aabb[i*4+0]=mnx; g_aabb[i*4+1]=mxx; g_aabb[i*4+2]=mny; g_aabb[i*4+3]=mxy;
        if (lab >= 0 && lab < NCLS) atomicAdd(&s_cc[lab], 1);
    }
    __syncthreads();

    // ---- class CSR + stage AABBs into sk space ----
    float* s_aabb = (float*)sk;                 // 16KB (sk dead)
    int*   s_cls  = (int*)(s_aabb + TOPK*4);
    if (tid == 0) {
        int acc = 0;
        for (int c = 0; c < NCLS; c++) { s_off[c] = acc; acc += s_cc[c]; }
        s_off[NCLS] = acc;
    }
    __syncthreads();
    for (int i = tid; i < TOPK; i += blockDim.x) {
        ((float4*)s_aabb)[i] = ((const float4*)g_aabb)[i];
        int lab = g_lab[i];
        if (lab >= 0 && lab < NCLS) {
            int pos = atomicAdd(&s_fill[lab], 1);
            s_cls[s_off[lab] + pos] = i;
        }
    }
    __syncthreads();

    // ---- AABB sieve -> global worklist ----
    for (int c = 0; c < NCLS; c++) {
        int n = s_cc[c];
        if (n < 2) continue;
        const int* cl = &s_cls[s_off[c]];
        for (int t = tid; t < n*n; t += blockDim.x) {
            int i_ = t / n, j_ = t - i_ * n;
            if (i_ >= j_) continue;
            int a = cl[i_], b = cl[j_];
            if (a > b) { int tmp = a; a = b; b = tmp; }
            const float M = 1.0f;
            if (s_aabb[a*4+0] > s_aabb[b*4+1] + M || s_aabb[b*4+0] > s_aabb[a*4+1] + M ||
                s_aabb[a*4+2] > s_aabb[b*4+3] + M || s_aabb[b*4+2] > s_aabb[a*4+3] + M) continue;
            unsigned pos = atomicAdd(&g_sel[4], 1u);
            if (pos < WCAP) g_work[pos] = ((unsigned)a << 16) | (unsigned)b;
        }
    }
}

// ---------------------------------------------------------------- warp-cooperative exact clip (register-resident, bitwise == scalar replica)
__device__ __forceinline__ float warp_inter_area(int bi, int bj, int lane) {
    const unsigned FULL = 0xffffffffu;
    const float eps = 1e-6f;
    const float ONEPE = 1.000001f;
    const float* A  = &g_nms[bi*5];
    const float* B  = &g_nms[bj*5];
    const float* cA = &g_corn[bi*8];
    const float* cB = &g_corn[bj*8];
    float ax0=cA[0], ay0=cA[1], ax1=cA[2], ay1=cA[3], ax2=cA[4], ay2=cA[5], ax3=cA[6], ay3=cA[7];
    float bx0=cB[0], by0=cB[1], bx1=cB[2], by1=cB[3], bx2=cB[4], by2=cB[5], bx3=cB[6], by3=cB[7];
    float Acx=A[0], Acy=A[1], Aw=A[2], Ah=A[3], Aa=A[4];
    float Bcx=B[0], Bcy=B[1], Bw=B[2], Bh=B[3], Ba=B[4];

    float dAx0=__fsub_rn(ax1,ax0), dAy0=__fsub_rn(ay1,ay0);
    float dAx1=__fsub_rn(ax2,ax1), dAy1=__fsub_rn(ay2,ay1);
    float dAx2=__fsub_rn(ax3,ax2), dAy2=__fsub_rn(ay3,ay2);
    float dAx3=__fsub_rn(ax0,ax3), dAy3=__fsub_rn(ay0,ay3);
    float dBx0=__fsub_rn(bx1,bx0), dBy0=__fsub_rn(by1,by0);
    float dBx1=__fsub_rn(bx2,bx1), dBy1=__fsub_rn(by2,by1);
    float dBx2=__fsub_rn(bx3,bx2), dBy2=__fsub_rn(by3,by2);
    float dBx3=__fsub_rn(bx0,bx3), dBy3=__fsub_rn(by0,by3);

    float px = 0.0f, py = 0.0f;
    bool  vl = false;
    if (lane < 8) {
        int  c4  = lane & 3;
        bool isA = lane < 4;
        float ptx = isA ? sel4(c4, ax0,ax1,ax2,ax3) : sel4(c4, bx0,bx1,bx2,bx3);
        float pty = isA ? sel4(c4, ay0,ay1,ay2,ay3) : sel4(c4, by0,by1,by2,by3);
        float tcx = isA ? Bcx : Acx;
        float tcy = isA ? Bcy : Acy;
        float tw  = isA ? Bw  : Aw;
        float th  = isA ? Bh  : Ah;
        float ta  = isA ? Ba  : Aa;
        float cc = cosf(ta), ss = sinf(ta);
        float rx = __fsub_rn(ptx, tcx), ry = __fsub_rn(pty, tcy);
        float xr = __fadd_rn(__fmul_rn(rx, cc), __fmul_rn(ry, ss));
        float yr = __fadd_rn(__fmul_rn(-rx, ss), __fmul_rn(ry, cc));
        float lw = __fadd_rn(__fmul_rn(tw, 0.5f), eps);
        float lh = __fadd_rn(__fmul_rn(th, 0.5f), eps);
        vl = (fabsf(xr) <= lw) && (fabsf(yr) <= lh);
        px = ptx; py = pty;
    } else if (lane < 24) {
        int ii = (lane - 8) >> 2, jj = (lane - 8) & 3;
        float axi = sel4(ii, ax0,ax1,ax2,ax3), ayi = sel4(ii, ay0,ay1,ay2,ay3);
        float dxi = sel4(ii, dAx0,dAx1,dAx2,dAx3), dyi = sel4(ii, dAy0,dAy1,dAy2,dAy3);
        float bxj = sel4(jj, bx0,bx1,bx2,bx3), byj = sel4(jj, by0,by1,by2,by3);
        float exj = sel4(jj, dBx0,dBx1,dBx2,dBx3), eyj = sel4(jj, dBy0,dBy1,dBy2,dBy3);
        float rx  = __fsub_rn(bxj, axi), ry = __fsub_rn(byj, ayi);
        float den = __fsub_rn(__fmul_rn(dxi, eyj), __fmul_rn(dyi, exj));
        float ad  = fabsf(den);
        float dens = (ad < 1e-9f) ? 1.0f : den;
        float t = __fsub_rn(__fmul_rn(rx, eyj), __fmul_rn(ry, exj)) / dens;
        float u = __fsub_rn(__fmul_rn(rx, dyi), __fmul_rn(ry, dxi)) / dens;
        vl = (ad > 1e-9f) && (t >= -eps) && (t <= ONEPE) && (u >= -eps) && (u <= ONEPE);
        px = __fadd_rn(axi, __fmul_rn(t, dxi));
        py = __fadd_rn(ayi, __fmul_rn(t, dyi));
    }

    unsigned bal = __ballot_sync(FULL, vl) & 0x00FFFFFFu;
    int cnt = __popc(bal);

    float f = vl ? 1.0f : 0.0f;
    float contx = __fmul_rn(px, f);
    float conty = __fmul_rn(py, f);
    float sx = 0.0f, sy = 0.0f;
#pragma unroll
    for (int m = 0; m < 24; m++) {
        float vx = __shfl_sync(FULL, contx, m);
        float vy = __shfl_sync(FULL, conty, m);
        sx = __fadd_rn(sx, vx);
        sy = __fadd_rn(sy, vy);
    }
    int cm = cnt > 1 ? cnt : 1;
    float cenx = sx / (float)cm, ceny = sy / (float)cm;

    int am = bal ? (__ffs(bal) - 1) : 0;
    float anx  = __shfl_sync(FULL, px, am);
    float anyy = __shfl_sync(FULL, py, am);

    float qx = vl ? px : anx;
    float qy = vl ? py : anyy;
    float ang = atan2f(__fsub_rn(qy, ceny), __fsub_rn(qx, cenx));

    int rank = (lane < 24) ? 0 : (100 + lane);
#pragma unroll
    for (int m = 0; m < 24; m++) {
        float am_ = __shfl_sync(FULL, ang, m);
        if (lane < 24 && m != lane) {
            bool less = (am_ < ang) || (am_ == ang && m < lane);
            rank += less ? 1 : 0;
        }
    }

    float X = 0.0f, Y = 0.0f;
#pragma unroll
    for (int m = 0; m < 24; m++) {
        int   rm = __shfl_sync(FULL, rank, m);
        float xm = __shfl_sync(FULL, qx, m);
        float ym = __shfl_sync(FULL, qy, m);
        if (rm == lane) { X = xm; Y = ym; }
    }
    int nxt = (lane == 23) ? 0 : lane + 1;
    float Xn = __shfl_sync(FULL, X, nxt);
    float Yn = __shfl_sync(FULL, Y, nxt);
    float term = __fsub_rn(__fmul_rn(X, Yn), __fmul_rn(Xn, Y));

    float ssum = 0.0f;
#pragma unroll
    for (int m = 0; m < 24; m++) {
        float tv = __shfl_sync(FULL, term, m);
        ssum = __fadd_rn(ssum, tv);
    }
    float area = __fmul_rn(0.5f, fabsf(ssum));
    return (cnt >= 3) ? area : 0.0f;
}

// ---------------------------------------------------------------- clips (warp-coop) + slot-compacted NMS + output (last block)
__global__ void __launch_bounds__(256) k_pairsH(float* __restrict__ out) {
    int tid  = threadIdx.x;
    int lane = tid & 31;
    unsigned W = g_sel[4];
    if (W > WCAP) W = WCAP;
    unsigned gw = (unsigned)(blockIdx.x * blockDim.x + tid) >> 5;
    unsigned nw = (unsigned)(gridDim.x * blockDim.x) >> 5;
    for (unsigned c = gw; c < W; c += nw) {
        unsigned e = g_work[c];
        int i = (int)(e >> 16), j = (int)(e & 0xFFFFu);
        float inter = warp_inter_area(i, j, lane);
        if (lane == 0) {
            float S   = __fadd_rn(__fsub_rn(__fadd_rn(g_area[i], g_area[j]), inter), 1e-6f);
            float iou = inter / S;
            if (iou > 0.5f) {
                unsigned pos = atomicAdd(&g_sel[5], 1u);
                if (pos < SPCAP) g_supPairs[pos] = e;
            }
        }
    }

    __shared__ int isLast;
    __threadfence();
    __syncthreads();
    if (tid == 0) {
        unsigned t = atomicAdd(&g_sel[1], 1u);
        isLast = (t == gridDim.x - 1);
    }
    __syncthreads();
    if (!isLast) return;
    __threadfence();

    __shared__ unsigned keepW[32];
    __shared__ unsigned raW[32];
    __shared__ unsigned wbase[32];
    __shared__ unsigned mask[MAXSLOTS * 32];     // 32KB
    __shared__ int lst[DETS];
    __shared__ int kcnt;
    __shared__ int nslots;
    if (tid < 32) { keepW[tid] = 0u; raW[tid] = 0u; }
    __syncthreads();
    for (int i = tid; i < TOPK; i += blockDim.x)
        if (g_topVal[i] > neginf()) atomicOr(&keepW[i >> 5], 1u << (i & 31));
    unsigned P = g_sel[5];
    if (P > SPCAP) P = SPCAP;
    for (unsigned p = (unsigned)tid; p < P; p += (unsigned)blockDim.x) {
        unsigned i = g_supPairs[p] >> 16;
        atomicOr(&raW[i >> 5], 1u << (i & 31));
    }
    __syncthreads();
    // slot prefix: wbase[w] = #suppressing rows in words < w
    if (tid < 32) {
        unsigned cnt = __popc(raW[tid]);
        unsigned ex = cnt;
#pragma unroll
        for (int d = 1; d < 32; d <<= 1) {
            unsigned v = __shfl_up_sync(0xffffffffu, ex, d);
            if (tid >= d) ex += v;
        }
        wbase[tid] = ex - cnt;                   // exclusive
        if (tid == 31) nslots = (int)ex;
    }
    __syncthreads();
    int NS = nslots;
    if (NS <= MAXSLOTS) {
        for (int k = tid; k < NS * 32; k += blockDim.x) mask[k] = 0u;
        __syncthreads();
        for (unsigned p = (unsigned)tid; p < P; p += (unsigned)blockDim.x) {
            unsigned e = g_supPairs[p];
            unsigned i = e >> 16, j = e & 0xFFFFu;
            unsigned w = i >> 5, b = i & 31;
            unsigned slot = wbase[w] + __popc(raW[w] & ((1u << b) - 1u));
            atomicOr(&mask[slot * 32 + (j >> 5)], 1u << (j & 31));
        }
        __syncthreads();
        if (tid < 32) {
            int s = 0;
            for (int w = 0; w < 32; w++) {
                unsigned rb = raW[w];
                while (rb) {
                    int b = __ffs(rb) - 1;
                    rb &= rb - 1;
                    bool kept = (keepW[w] >> b) & 1u;
                    if (kept) keepW[tid] &= ~mask[s * 32 + tid];
                    s++;
                    __syncwarp();
                }
            }
        }
    } else if (tid == 0) {
        // improbable overflow fallback: serial pair scan (correct, slow)
        for (int w = 0; w < 32; w++) {
            unsigned rb = raW[w];
            while (rb) {
                int b = __ffs(rb) - 1;
                rb &= rb - 1;
                int i = w * 32 + b;
                if (keepW[w] & (1u << b)) {
                    for (unsigned p = 0; p < P; p++) {
                        unsigned e = g_supPairs[p];
                        if ((int)(e >> 16) == i) {
                            int j = (int)(e & 0xFFFFu);
                            keepW[j >> 5] &= ~(1u << (j & 31));
                        }
                    }
                }
            }
        }
    }
    __syncthreads();

    if (tid == 0) {
        int p = 0;
        for (int w = 0; w < 32 && p < DETS; w++) {
            unsigned m = keepW[w];
            while (m && p < DETS) {
                int b = __ffs(m) - 1;
                m &= m - 1;
                lst[p++] = w * 32 + b;
            }
        }
        kcnt = p;
        g_sel[1] = 0;
    }
    __syncthreads();

    for (int r = tid; r < DETS; r += blockDim.x) {
        if (r < kcnt) {
            int i = lst[r];
#pragma unroll
            for (int k = 0; k < 5; k++) out[r*5+k] = g_bk[i*5+k];
            out[DETS*5 + r] = (float)g_lab[i];
            out[DETS*6 + r] = g_topVal[i];
        } else {
#pragma unroll
            for (int k = 0; k < 5; k++) out[r*5+k] = 0.0f;
            out[DETS*5 + r] = -1.0f;
            out[DETS*6 + r] = 0.0f;
        }
    }
}

// ---------------------------------------------------------------- launcher
extern "C" void kernel_launch(void* const* d_in, const int* in_sizes, int n_in,
                              void* d_out, int out_size) {
    const float* boxes  = (const float*)d_in[0];
    const float* scores = (const float*)d_in[1];
    const int*   labels = (const int*)d_in[2];
    int n = in_sizes[1];
    int n4 = n / 4;

    k_fast   <<<FAST_GRID, 256>>>((const float4*)scores, n4);
    k_histcmp<<<HIST_GRID, 256>>>((const float4*)scores, n4);
    k_selprep<<<SEL_GRID, 256>>>(boxes, labels);
    k_pairsH <<<PAIR_GRID, 256>>>((float*)d_out);
}

// round 12
// speedup vs baseline: 3.0155x; 1.6304x over previous
#include <cuda_runtime.h>
#include <stdint.h>
#include <math.h>

#define TOPK 1000
#define DETS 300
#define NB    4608          // fallback bins via fb>>13 - BASE
#define BASE  125542        // 0x3D4CCCCD >> 13  (0.05f)
#define CAND_CAP 32768
#define SELCAP   6144
#define NCLS  80
#define CLSCAP 1024
#define WCAP  8192
#define SPCAP 8192
#define MAXSLOTS 256
#define FAST_T 0.999f
#define GRID  132
#define NTHR  256

__device__ unsigned          g_barCount;
__device__ volatile unsigned g_barSense;
__device__ unsigned          g_hist1[NB];
__device__ unsigned          g_sel[8];     // [0]=B1 bin  [2]=cand cnt  [4]=work cnt  [5]=sup cnt
__device__ unsigned long long g_cand[CAND_CAP];
__device__ unsigned          g_work[WCAP];
__device__ unsigned          g_supPairs[SPCAP];
__device__ int               g_topIdx[TOPK];
__device__ float             g_topVal[TOPK];
__device__ float             g_bk[TOPK*5];
__device__ float             g_nms[TOPK*5];
__device__ float             g_corn[TOPK*8];
__device__ float             g_aabb[TOPK*4];
__device__ float             g_area[TOPK];
__device__ int               g_clsCnt[NCLS];
__device__ int               g_clsIdx[NCLS*CLSCAP];
__device__ int               g_lab[TOPK];

__device__ __forceinline__ float neginf() { return __int_as_float(0xff800000); }

__device__ __forceinline__ int bin_of(unsigned fb) {
    int b = (int)(fb >> 13) - BASE;
    if (b < 0) b = 0;
    if (b > NB - 1) b = NB - 1;
    return b;
}

__device__ __forceinline__ float sel4(int i, float a, float b, float c, float d) {
    return (i == 0) ? a : (i == 1) ? b : (i == 2) ? c : d;
}

// sense-reversing software grid barrier (all blocks co-resident: GRID <= #SM)
__device__ __forceinline__ void gbar(unsigned* shSense) {
    __syncthreads();
    if (threadIdx.x == 0) {
        unsigned s = *shSense ^ 1u;
        *shSense = s;
        __threadfence();
        unsigned arrived = atomicAdd(&g_barCount, 1u) + 1u;
        if (arrived == (unsigned)gridDim.x) {
            atomicExch(&g_barCount, 0u);
            __threadfence();
            g_barSense = s;
        } else {
            while (g_barSense != s) __nanosleep(64);
        }
        __threadfence();
    }
    __syncthreads();
}

// ---------------------------------------------------------------- warp-cooperative exact clip (bitwise == scalar reference replica)
__device__ __forceinline__ float warp_inter_area(int bi, int bj, int lane) {
    const unsigned FULL = 0xffffffffu;
    const float eps = 1e-6f;
    const float ONEPE = 1.000001f;
    const float* A  = &g_nms[bi*5];
    const float* B  = &g_nms[bj*5];
    const float* cA = &g_corn[bi*8];
    const float* cB = &g_corn[bj*8];
    float ax0=cA[0], ay0=cA[1], ax1=cA[2], ay1=cA[3], ax2=cA[4], ay2=cA[5], ax3=cA[6], ay3=cA[7];
    float bx0=cB[0], by0=cB[1], bx1=cB[2], by1=cB[3], bx2=cB[4], by2=cB[5], bx3=cB[6], by3=cB[7];
    float Acx=A[0], Acy=A[1], Aw=A[2], Ah=A[3], Aa=A[4];
    float Bcx=B[0], Bcy=B[1], Bw=B[2], Bh=B[3], Ba=B[4];

    float dAx0=__fsub_rn(ax1,ax0), dAy0=__fsub_rn(ay1,ay0);
    float dAx1=__fsub_rn(ax2,ax1), dAy1=__fsub_rn(ay2,ay1);
    float dAx2=__fsub_rn(ax3,ax2), dAy2=__fsub_rn(ay3,ay2);
    float dAx3=__fsub_rn(ax0,ax3), dAy3=__fsub_rn(ay0,ay3);
    float dBx0=__fsub_rn(bx1,bx0), dBy0=__fsub_rn(by1,by0);
    float dBx1=__fsub_rn(bx2,bx1), dBy1=__fsub_rn(by2,by1);
    float dBx2=__fsub_rn(bx3,bx2), dBy2=__fsub_rn(by3,by2);
    float dBx3=__fsub_rn(bx0,bx3), dBy3=__fsub_rn(by0,by3);

    float px = 0.0f, py = 0.0f;
    bool  vl = false;
    if (lane < 8) {
        int  c4  = lane & 3;
        bool isA = lane < 4;
        float ptx = isA ? sel4(c4, ax0,ax1,ax2,ax3) : sel4(c4, bx0,bx1,bx2,bx3);
        float pty = isA ? sel4(c4, ay0,ay1,ay2,ay3) : sel4(c4, by0,by1,by2,by3);
        float tcx = isA ? Bcx : Acx;
        float tcy = isA ? Bcy : Acy;
        float tw  = isA ? Bw  : Aw;
        float th  = isA ? Bh  : Ah;
        float ta  = isA ? Ba  : Aa;
        float cc = cosf(ta), ss = sinf(ta);
        float rx = __fsub_rn(ptx, tcx), ry = __fsub_rn(pty, tcy);
        float xr = __fadd_rn(__fmul_rn(rx, cc), __fmul_rn(ry, ss));
        float yr = __fadd_rn(__fmul_rn(-rx, ss), __fmul_rn(ry, cc));
        float lw = __fadd_rn(__fmul_rn(tw, 0.5f), eps);
        float lh = __fadd_rn(__fmul_rn(th, 0.5f), eps);
        vl = (fabsf(xr) <= lw) && (fabsf(yr) <= lh);
        px = ptx; py = pty;
    } else if (lane < 24) {
        int ii = (lane - 8) >> 2, jj = (lane - 8) & 3;
        float axi = sel4(ii, ax0,ax1,ax2,ax3), ayi = sel4(ii, ay0,ay1,ay2,ay3);
        float dxi = sel4(ii, dAx0,dAx1,dAx2,dAx3), dyi = sel4(ii, dAy0,dAy1,dAy2,dAy3);
        float bxj = sel4(jj, bx0,bx1,bx2,bx3), byj = sel4(jj, by0,by1,by2,by3);
        float exj = sel4(jj, dBx0,dBx1,dBx2,dBx3), eyj = sel4(jj, dBy0,dBy1,dBy2,dBy3);
        float rx  = __fsub_rn(bxj, axi), ry = __fsub_rn(byj, ayi);
        float den = __fsub_rn(__fmul_rn(dxi, eyj), __fmul_rn(dyi, exj));
        float ad  = fabsf(den);
        float dens = (ad < 1e-9f) ? 1.0f : den;
        float t = __fsub_rn(__fmul_rn(rx, eyj), __fmul_rn(ry, exj)) / dens;
        float u = __fsub_rn(__fmul_rn(rx, dyi), __fmul_rn(ry, dxi)) / dens;
        vl = (ad > 1e-9f) && (t >= -eps) && (t <= ONEPE) && (u >= -eps) && (u <= ONEPE);
        px = __fadd_rn(axi, __fmul_rn(t, dxi));
        py = __fadd_rn(ayi, __fmul_rn(t, dyi));
    }

    unsigned bal = __ballot_sync(FULL, vl) & 0x00FFFFFFu;
    int cnt = __popc(bal);

    float f = vl ? 1.0f : 0.0f;
    float contx = __fmul_rn(px, f);
    float conty = __fmul_rn(py, f);
    float sx = 0.0f, sy = 0.0f;
#pragma unroll
    for (int m = 0; m < 24; m++) {
        float vx = __shfl_sync(FULL, contx, m);
        float vy = __shfl_sync(FULL, conty, m);
        sx = __fadd_rn(sx, vx);
        sy = __fadd_rn(sy, vy);
    }
    int cm = cnt > 1 ? cnt : 1;
    float cenx = sx / (float)cm, ceny = sy / (float)cm;

    int am = bal ? (__ffs(bal) - 1) : 0;
    float anx  = __shfl_sync(FULL, px, am);
    float anyy = __shfl_sync(FULL, py, am);

    float qx = vl ? px : anx;
    float qy = vl ? py : anyy;
    float ang = atan2f(__fsub_rn(qy, ceny), __fsub_rn(qx, cenx));

    int rank = (lane < 24) ? 0 : (100 + lane);
#pragma unroll
    for (int m = 0; m < 24; m++) {
        float am_ = __shfl_sync(FULL, ang, m);
        if (lane < 24 && m != lane) {
            bool less = (am_ < ang) || (am_ == ang && m < lane);
            rank += less ? 1 : 0;
        }
    }

    float X = 0.0f, Y = 0.0f;
#pragma unroll
    for (int m = 0; m < 24; m++) {
        int   rm = __shfl_sync(FULL, rank, m);
        float xm = __shfl_sync(FULL, qx, m);
        float ym = __shfl_sync(FULL, qy, m);
        if (rm == lane) { X = xm; Y = ym; }
    }
    int nxt = (lane == 23) ? 0 : lane + 1;
    float Xn = __shfl_sync(FULL, X, nxt);
    float Yn = __shfl_sync(FULL, Y, nxt);
    float term = __fsub_rn(__fmul_rn(X, Yn), __fmul_rn(Xn, Y));

    float ssum = 0.0f;
#pragma unroll
    for (int m = 0; m < 24; m++) {
        float tv = __shfl_sync(FULL, term, m);
        ssum = __fadd_rn(ssum, tv);
    }
    float area = __fmul_rn(0.5f, fabsf(ssum));
    return (cnt >= 3) ? area : 0.0f;
}

// ---------------------------------------------------------------- ONE persistent kernel, software grid barriers
extern __shared__ unsigned char dynbuf[];   // 49152 B

__global__ void __launch_bounds__(NTHR)
k_all(const float* __restrict__ boxes, const float4* __restrict__ sc4,
      const int* __restrict__ labels, float* __restrict__ out, int n4) {
    __shared__ unsigned shSense;
    __shared__ unsigned shC;
    __shared__ int shSkip;
    int tid = threadIdx.x;
    int bid = blockIdx.x;
    if (tid == 0) shSense = 0u;
    __syncthreads();

    // ---------------- P1: fast compact (s > FAST_T) ----------------
    {
        int i0 = bid * NTHR + tid;
        int S  = GRID * NTHR;
        for (int p = i0; p < n4; p += 4 * S) {
            int p1 = p + S, p2 = p + 2*S, p3 = p + 3*S;
            float4 v0 = sc4[p];
            float4 v1 = (p1 < n4) ? sc4[p1] : make_float4(0,0,0,0);
            float4 v2 = (p2 < n4) ? sc4[p2] : make_float4(0,0,0,0);
            float4 v3 = (p3 < n4) ? sc4[p3] : make_float4(0,0,0,0);
            float vs[16] = { v0.x,v0.y,v0.z,v0.w, v1.x,v1.y,v1.z,v1.w,
                             v2.x,v2.y,v2.z,v2.w, v3.x,v3.y,v3.z,v3.w };
            int  pq[4] = { p, p1, p2, p3 };
#pragma unroll
            for (int l = 0; l < 16; l++) {
                float s = vs[l];
                if (s > FAST_T) {
                    unsigned pos = atomicAdd(&g_sel[2], 1u);
                    if (pos < CAND_CAP) {
                        unsigned idx = (unsigned)(pq[l >> 2] * 4 + (l & 3));
                        g_cand[pos] = ((unsigned long long)__float_as_uint(s) << 32) |
                                      (unsigned long long)(0xFFFFFFFFu - idx);
                    }
                }
            }
        }
    }
    gbar(&shSense);                                            // B1

    // ---------------- P2: skip decision + default init ----------------
    if (tid == 0) {
        unsigned ct = g_sel[2];
        shSkip = (ct >= TOPK && ct <= CAND_CAP) ? 1 : 0;
    }
    __syncthreads();
    int skip = shSkip;                                         // grid-uniform
    for (int i = bid * NTHR + tid; i < TOPK; i += GRID * NTHR) {
        g_topIdx[i] = -1;
        g_topVal[i] = neginf();
    }
    if (!skip) {
        // ---- fallback (correct, barrier-balanced; not hit on this data) ----
        unsigned* h = (unsigned*)dynbuf;
        for (int k = tid; k < NB; k += NTHR) h[k] = 0u;
        __syncthreads();
        for (int p = bid * NTHR + tid; p < n4; p += GRID * NTHR) {
            float4 v = sc4[p];
            float vs[4] = { v.x, v.y, v.z, v.w };
#pragma unroll
            for (int l = 0; l < 4; l++)
                if (vs[l] > 0.05f) atomicAdd(&h[bin_of(__float_as_uint(vs[l]))], 1u);
        }
        __syncthreads();
        for (int k = tid; k < NB; k += NTHR) {
            unsigned v = h[k];
            if (v) atomicAdd(&g_hist1[k], v);
        }
        gbar(&shSense);                                        // Bf1
        if (bid == 0 && tid == 0) {
            unsigned cum = 0; int B1 = -1;
            for (int b = NB - 1; b >= 0; b--) {
                unsigned c = g_hist1[b];
                if (cum + c >= TOPK) { B1 = b; break; }
                cum += c;
            }
            if (B1 < 0) B1 = 0;
            g_sel[0] = (unsigned)B1;
            g_sel[2] = 0u;
        }
        gbar(&shSense);                                        // Bf2
        {
            unsigned B1 = g_sel[0];
            for (int p = bid * NTHR + tid; p < n4; p += GRID * NTHR) {
                float4 v = sc4[p];
                float vs[4] = { v.x, v.y, v.z, v.w };
#pragma unroll
                for (int l = 0; l < 4; l++) {
                    float s = vs[l];
                    if (s > 0.05f) {
                        unsigned fb = __float_as_uint(s);
                        if (bin_of(fb) >= (int)B1) {
                            unsigned pos = atomicAdd(&g_sel[2], 1u);
                            if (pos < CAND_CAP) {
                                unsigned idx = (unsigned)(p * 4 + l);
                                g_cand[pos] = ((unsigned long long)fb << 32) |
                                              (unsigned long long)(0xFFFFFFFFu - idx);
                            }
                        }
                    }
                }
            }
        }
        gbar(&shSense);                                        // Bf3
        gbar(&shSense);                                        // Bf4 (parity pad)
    }
    gbar(&shSense);                                            // B2

    // ---------------- P3: select (16-lane cooperative rank, uniform iterations) ----------------
    {
        if (tid == 0) shC = g_sel[2];
        __syncthreads();
        unsigned C = shC;
        if (C > CAND_CAP) C = CAND_CAP;
        unsigned long long* sk = (unsigned long long*)dynbuf;  // 49152 B = SELCAP u64
        bool small = (C <= SELCAP);
        const unsigned long long* base;
        if (small) {
            for (unsigned k = (unsigned)tid; k < C; k += NTHR) sk[k] = g_cand[k];
            base = sk;
        } else {
            base = g_cand;
        }
        __syncthreads();
        unsigned lane  = (unsigned)tid & 15u;
        unsigned gidx  = (unsigned)(bid * NTHR + tid) >> 4;
        unsigned cstr  = (unsigned)(GRID * NTHR) >> 4;
        unsigned nIter = (C + cstr - 1) / cstr;                // uniform across grid
        for (unsigned it = 0; it < nIter; it++) {
            unsigned c = gidx + it * cstr;
            bool act = (c < C);
            unsigned long long key = act ? base[c] : 0ULL;
            unsigned rank = 0;
            unsigned k = lane;
            for (; k + 48 < C; k += 64) {
                unsigned long long a0 = base[k], a1 = base[k+16], a2 = base[k+32], a3 = base[k+48];
                rank += (a0 > key) + (a1 > key) + (a2 > key) + (a3 > key);
            }
            for (; k < C; k += 16) rank += (base[k] > key) ? 1u : 0u;
            rank += __shfl_down_sync(0xffffffffu, rank, 8, 16);
            rank += __shfl_down_sync(0xffffffffu, rank, 4, 16);
            rank += __shfl_down_sync(0xffffffffu, rank, 2, 16);
            rank += __shfl_down_sync(0xffffffffu, rank, 1, 16);
            if (act && lane == 0 && rank < TOPK) {
                g_topIdx[rank] = (int)(0xFFFFFFFFu - (unsigned)(key & 0xFFFFFFFFull));
                g_topVal[rank] = __uint_as_float((unsigned)(key >> 32));
            }
        }
    }
    gbar(&shSense);                                            // B3

    // ---------------- P4: prep (spread over grid) ----------------
    for (int i = bid * NTHR + tid; i < TOPK; i += GRID * NTHR) {
        int idx = g_topIdx[i];
        if (idx < 0) { g_lab[i] = -1 - NCLS; g_area[i] = 0.0f; continue; }
        float cx = boxes[idx*5+0], cy = boxes[idx*5+1];
        float w  = boxes[idx*5+2], h  = boxes[idx*5+3];
        float a  = boxes[idx*5+4];
        g_bk[i*5+0]=cx; g_bk[i*5+1]=cy; g_bk[i*5+2]=w; g_bk[i*5+3]=h; g_bk[i*5+4]=a;
        int lab = labels[idx];
        g_lab[i] = lab;
        float off = __fmul_rn((float)lab, 10000.0f);
        float cxo = __fadd_rn(cx, off);
        float cyo = __fadd_rn(cy, off);
        g_nms[i*5+0]=cxo; g_nms[i*5+1]=cyo; g_nms[i*5+2]=w; g_nms[i*5+3]=h; g_nms[i*5+4]=a;
        g_area[i] = __fmul_rn(w, h);
        float c = cosf(a), s = sinf(a);
        float dx = __fmul_rn(w, 0.5f), dy = __fmul_rn(h, 0.5f);
        float ox[4] = { dx, -dx, -dx,  dx };
        float oy[4] = { dy,  dy, -dy, -dy };
        float mnx =  3.4e38f, mxx = -3.4e38f, mny = 3.4e38f, mxy = -3.4e38f;
#pragma unroll
        for (int j = 0; j < 4; j++) {
            float x = __fsub_rn(__fadd_rn(cxo, __fmul_rn(ox[j], c)), __fmul_rn(oy[j], s));
            float y = __fadd_rn(__fadd_rn(cyo, __fmul_rn(ox[j], s)), __fmul_rn(oy[j], c));
            g_corn[i*8 + 2*j]     = x;
            g_corn[i*8 + 2*j + 1] = y;
            mnx = fminf(mnx, x); mxx = fmaxf(mxx, x);
            mny = fminf(mny, y); mxy = fmaxf(mxy, y);
        }
        g_aabb[i*4+0]=mnx; g_aabb[i*4+1]=mxx; g_aabb[i*4+2]=mny; g_aabb[i*4+3]=mxy;
        if (lab >= 0 && lab < NCLS) {
            int pos = atomicAdd(&g_clsCnt[lab], 1);
            if (pos < CLSCAP) g_clsIdx[lab*CLSCAP + pos] = i;
        }
    }
    gbar(&shSense);                                            // B4

    // ---------------- P5: AABB sieve (classes spread over blocks) ----------------
    for (int c = bid; c < NCLS; c += GRID) {
        int n = g_clsCnt[c];
        if (n > CLSCAP) n = CLSCAP;
        if (n < 2) continue;
        const int* cl = &g_clsIdx[c*CLSCAP];
        for (int t = tid; t < n*n; t += NTHR) {
            int i_ = t / n, j_ = t - i_ * n;
            if (i_ >= j_) continue;
            int a = cl[i_], b = cl[j_];
            if (a > b) { int tmp = a; a = b; b = tmp; }
            const float M = 1.0f;
            if (g_aabb[a*4+0] > g_aabb[b*4+1] + M || g_aabb[b*4+0] > g_aabb[a*4+1] + M ||
                g_aabb[a*4+2] > g_aabb[b*4+3] + M || g_aabb[b*4+2] > g_aabb[a*4+3] + M) continue;
            unsigned pos = atomicAdd(&g_sel[4], 1u);
            if (pos < WCAP) g_work[pos] = ((unsigned)a << 16) | (unsigned)b;
        }
    }
    gbar(&shSense);                                            // B5

    // ---------------- P6: warp-cooperative clips (warp-uniform loop) ----------------
    {
        int lane = tid & 31;
        unsigned W = g_sel[4];
        if (W > WCAP) W = WCAP;
        unsigned gw = (unsigned)(bid * NTHR + tid) >> 5;
        unsigned nw = (unsigned)(GRID * NTHR) >> 5;
        for (unsigned c = gw; c < W; c += nw) {
            unsigned e = g_work[c];
            int i = (int)(e >> 16), j = (int)(e & 0xFFFFu);
            float inter = warp_inter_area(i, j, lane);
            if (lane == 0) {
                float S   = __fadd_rn(__fsub_rn(__fadd_rn(g_area[i], g_area[j]), inter), 1e-6f);
                float iou = inter / S;
                if (iou > 0.5f) {
                    unsigned pos = atomicAdd(&g_sel[5], 1u);
                    if (pos < SPCAP) g_supPairs[pos] = e;
                }
            }
        }
    }
    gbar(&shSense);                                            // B6 (even barrier count; sense returns to 0)

    // ---------------- P7: block 0 — slot-compacted NMS + output + self-clean ----------------
    if (bid != 0) return;
    {
        __shared__ unsigned keepW[32];
        __shared__ unsigned raW[32];
        __shared__ unsigned wbase[32];
        __shared__ int lst[DETS];
        __shared__ int kcnt;
        __shared__ int nslots;
        unsigned* mask = (unsigned*)dynbuf;                    // 32KB within dynbuf
        if (tid < 32) { keepW[tid] = 0u; raW[tid] = 0u; }
        __syncthreads();
        for (int i = tid; i < TOPK; i += NTHR)
            if (g_topVal[i] > neginf()) atomicOr(&keepW[i >> 5], 1u << (i & 31));
        unsigned P = g_sel[5];
        if (P > SPCAP) P = SPCAP;
        for (unsigned p = (unsigned)tid; p < P; p += NTHR) {
            unsigned i = g_supPairs[p] >> 16;
            atomicOr(&raW[i >> 5], 1u << (i & 31));
        }
        __syncthreads();
        if (tid < 32) {
            unsigned cnt = __popc(raW[tid]);
            unsigned ex = cnt;
#pragma unroll
            for (int d = 1; d < 32; d <<= 1) {
                unsigned v = __shfl_up_sync(0xffffffffu, ex, d);
                if (tid >= d) ex += v;
            }
            wbase[tid] = ex - cnt;
            if (tid == 31) nslots = (int)ex;
        }
        __syncthreads();
        int NS = nslots;
        if (NS <= MAXSLOTS) {
            for (int k = tid; k < NS * 32; k += NTHR) mask[k] = 0u;
            __syncthreads();
            for (unsigned p = (unsigned)tid; p < P; p += NTHR) {
                unsigned e = g_supPairs[p];
                unsigned i = e >> 16, j = e & 0xFFFFu;
                unsigned w = i >> 5, b = i & 31;
                unsigned slot = wbase[w] + __popc(raW[w] & ((1u << b) - 1u));
                atomicOr(&mask[slot * 32 + (j >> 5)], 1u << (j & 31));
            }
            __syncthreads();
            if (tid < 32) {
                int s = 0;
                for (int w = 0; w < 32; w++) {
                    unsigned rb = raW[w];
                    while (rb) {
                        int b = __ffs(rb) - 1;
                        rb &= rb - 1;
                        bool kept = (keepW[w] >> b) & 1u;
                        if (kept) keepW[tid] &= ~mask[s * 32 + tid];
                        s++;
                        __syncwarp();
                    }
                }
            }
        } else if (tid == 0) {
            for (int w = 0; w < 32; w++) {
                unsigned rb = raW[w];
                while (rb) {
                    int b = __ffs(rb) - 1;
                    rb &= rb - 1;
                    int i = w * 32 + b;
                    if (keepW[w] & (1u << b)) {
                        for (unsigned p = 0; p < P; p++) {
                            unsigned e = g_supPairs[p];
                            if ((int)(e >> 16) == i) {
                                int j = (int)(e & 0xFFFFu);
                                keepW[j >> 5] &= ~(1u << (j & 31));
                            }
                        }
                    }
                }
            }
        }
        __syncthreads();
        if (tid == 0) {
            int p = 0;
            for (int w = 0; w < 32 && p < DETS; w++) {
                unsigned m = keepW[w];
                while (m && p < DETS) {
                    int b = __ffs(m) - 1;
                    m &= m - 1;
                    lst[p++] = w * 32 + b;
                }
            }
            kcnt = p;
        }
        __syncthreads();
        for (int r = tid; r < DETS; r += NTHR) {
            if (r < kcnt) {
                int i = lst[r];
#pragma unroll
                for (int k = 0; k < 5; k++) out[r*5+k] = g_bk[i*5+k];
                out[DETS*5 + r] = (float)g_lab[i];
                out[DETS*6 + r] = g_topVal[i];
            } else {
#pragma unroll
                for (int k = 0; k < 5; k++) out[r*5+k] = 0.0f;
                out[DETS*5 + r] = -1.0f;
                out[DETS*6 + r] = 0.0f;
            }
        }
        // self-clean for next launch / replay
        for (int k = tid; k < 8; k += NTHR) g_sel[k] = 0u;
        for (int c = tid; c < NCLS; c += NTHR) g_clsCnt[c] = 0;
        if (!skip) for (int k = tid; k < NB; k += NTHR) g_hist1[k] = 0u;
    }
}

// ---------------------------------------------------------------- launcher: ONE kernel
extern "C" void kernel_launch(void* const* d_in, const int* in_sizes, int n_in,
                              void* d_out, int out_size) {
    const float* boxes  = (const float*)d_in[0];
    const float* scores = (const float*)d_in[1];
    const int*   labels = (const int*)d_in[2];
    int n = in_sizes[1];
    int n4 = n / 4;

    static const int DYN = SELCAP * 8;   // 49152 B
    cudaFuncSetAttribute(k_all, cudaFuncAttributeMaxDynamicSharedMemorySize, DYN);
    k_all<<<GRID, NTHR, DYN>>>(boxes, (const float4*)scores, labels, (float*)d_out, n4);
}